// round 2
// baseline (speedup 1.0000x reference)
#include <cuda_runtime.h>
#include <cuda_bf16.h>
#include <math.h>

// ---------------- problem constants ----------------
#define BATCH   4
#define NSEQ    512
#define NDIM    1024
#define EDIM    64
#define HEADS   16
#define DOTD    64
#define FFN_H   2048
#define FFN_E   128
#define BN      (BATCH*NSEQ)          // 2048 token rows
#define NN      (NSEQ*NSEQ)           // 262144 per batch
#define BHN     (BATCH*HEADS)         // 64
#define EROWS   ((size_t)BATCH*NSEQ*NSEQ) // 1048576 edge rows
#define H_OUT_ELEMS (BN*NDIM)         // 2097152

// ---------------- scratch (device globals; no allocs allowed) ----------------
__device__ float g_hln [BN*NDIM];
__device__ float g_qkv [BN*3*NDIM];
__device__ float g_E   [(size_t)BHN*NN];   // (b*16+h, l*512+m)
__device__ float g_gate[(size_t)BHN*NN];
__device__ float g_H   [(size_t)BHN*NN];   // H_hat = clip(A)+E
__device__ float g_At  [(size_t)BHN*NN];   // softmax*gates
__device__ float g_vatt[BN*NDIM];
__device__ float g_h1  [BN*NDIM];          // h after O_h + residual
__device__ float g_h2  [BN*NDIM];          // LN of g_h1
__device__ float g_act [BN*FFN_H];

// ---------------- LayerNorm over 1024 ----------------
__global__ void __launch_bounds__(256) ln1024_kernel(
    const float* __restrict__ x, const float* __restrict__ g,
    const float* __restrict__ b, float* __restrict__ y)
{
    int row = blockIdx.x, t = threadIdx.x;
    const float* xr = x + (size_t)row * NDIM;
    float v[4]; float s = 0.f;
#pragma unroll
    for (int i = 0; i < 4; i++) { v[i] = xr[t + i*256]; s += v[i]; }
    __shared__ float red[8];
    int lane = t & 31, w = t >> 5;
#pragma unroll
    for (int o = 16; o; o >>= 1) s += __shfl_xor_sync(0xffffffff, s, o);
    if (lane == 0) red[w] = s;
    __syncthreads();
    float tot = 0.f;
#pragma unroll
    for (int i = 0; i < 8; i++) tot += red[i];
    float mu = tot * (1.0f/NDIM);
    __syncthreads();
    float q = 0.f;
#pragma unroll
    for (int i = 0; i < 4; i++) { float d = v[i]-mu; q += d*d; }
#pragma unroll
    for (int o = 16; o; o >>= 1) q += __shfl_xor_sync(0xffffffff, q, o);
    if (lane == 0) red[w] = q;
    __syncthreads();
    float qt = 0.f;
#pragma unroll
    for (int i = 0; i < 8; i++) qt += red[i];
    float rs = rsqrtf(qt * (1.0f/NDIM) + 1e-5f);
    float* yr = y + (size_t)row * NDIM;
#pragma unroll
    for (int i = 0; i < 4; i++) {
        int c = t + i*256;
        yr[c] = (v[i]-mu)*rs*g[c] + b[c];
    }
}

// ---------------- tf32 helpers ----------------
__device__ __forceinline__ float f2tf(float x) {
    unsigned r;
    asm("cvt.rna.tf32.f32 %0, %1;" : "=r"(r) : "f"(x));
    return __uint_as_float(r);
}

__device__ __forceinline__ void mma_tf32(float* c, const unsigned* a, const unsigned* b) {
    asm volatile(
        "mma.sync.aligned.m16n8k8.row.col.f32.tf32.tf32.f32 "
        "{%0,%1,%2,%3}, {%4,%5,%6,%7}, {%8,%9}, {%0,%1,%2,%3};\n"
        : "+f"(c[0]), "+f"(c[1]), "+f"(c[2]), "+f"(c[3])
        : "r"(a[0]), "r"(a[1]), "r"(a[2]), "r"(a[3]), "r"(b[0]), "r"(b[1]));
}

// ---------------- tf32 tensor-core GEMM: C = act(A@W + bias) (+res) ----------------
// 128x128 tile, BK=16, 256 threads (8 warps), warp tile 32x64.
#define AS_LD 17
#define BS_LD 132
__global__ void __launch_bounds__(256, 2) gemm_tc_kernel(
    const float* __restrict__ A, const float* __restrict__ W,
    const float* __restrict__ bias, const float* __restrict__ res,
    float* __restrict__ C, int M, int N, int K, int act)
{
    __shared__ float As[2][128*AS_LD];
    __shared__ float Bs[2][16*BS_LD];

    int t = threadIdx.x;
    int lane = t & 31;
    int w = t >> 5;
    int wm = w & 3;            // 4 m-tiles of 32 rows
    int wn = w >> 2;           // 2 n-tiles of 64 cols
    int qr = lane >> 2;        // 0..7
    int qc = lane & 3;         // 0..3
    int n0 = blockIdx.x * 128, m0 = blockIdx.y * 128;

    int arow = t >> 1;             // 0..127
    int acol = (t & 1) * 8;        // 0 or 8
    int brow = t >> 4;             // 0..15
    int bcol = (t & 15) * 8;       // 0..120

    const float* Aptr = A + (size_t)(m0 + arow)*K + acol;
    const float* Bptr = W + (size_t)brow*N + n0 + bcol;

    float acc[2][8][4];
#pragma unroll
    for (int i = 0; i < 2; i++)
#pragma unroll
        for (int j = 0; j < 8; j++)
#pragma unroll
            for (int k = 0; k < 4; k++) acc[i][j][k] = 0.f;

    int KT = K / 16;
    float4 ra0, ra1, rb0, rb1;
    ra0 = *(const float4*)(Aptr + 0);
    ra1 = *(const float4*)(Aptr + 4);
    rb0 = *(const float4*)(Bptr + 0);
    rb1 = *(const float4*)(Bptr + 4);
    {
        float* as = As[0]; float* bs = Bs[0];
        int sa = arow*AS_LD + acol;
        as[sa+0]=f2tf(ra0.x); as[sa+1]=f2tf(ra0.y); as[sa+2]=f2tf(ra0.z); as[sa+3]=f2tf(ra0.w);
        as[sa+4]=f2tf(ra1.x); as[sa+5]=f2tf(ra1.y); as[sa+6]=f2tf(ra1.z); as[sa+7]=f2tf(ra1.w);
        int sb = brow*BS_LD + bcol;
        bs[sb+0]=f2tf(rb0.x); bs[sb+1]=f2tf(rb0.y); bs[sb+2]=f2tf(rb0.z); bs[sb+3]=f2tf(rb0.w);
        bs[sb+4]=f2tf(rb1.x); bs[sb+5]=f2tf(rb1.y); bs[sb+6]=f2tf(rb1.z); bs[sb+7]=f2tf(rb1.w);
    }
    __syncthreads();

    for (int kt = 0; kt < KT; kt++) {
        int cur = kt & 1;
        if (kt + 1 < KT) {
            int k0 = (kt + 1) * 16;
            ra0 = *(const float4*)(Aptr + k0);
            ra1 = *(const float4*)(Aptr + k0 + 4);
            rb0 = *(const float4*)(Bptr + (size_t)k0*N);
            rb1 = *(const float4*)(Bptr + (size_t)k0*N + 4);
        }
        const float* as = As[cur];
        const float* bs = Bs[cur];
#pragma unroll
        for (int ks = 0; ks < 2; ks++) {
            int k = ks * 8;
            unsigned af[2][4];
#pragma unroll
            for (int mt = 0; mt < 2; mt++) {
                int r0 = (wm*32 + mt*16 + qr) * AS_LD + k + qc;
                af[mt][0] = __float_as_uint(as[r0]);
                af[mt][1] = __float_as_uint(as[r0 + 8*AS_LD]);
                af[mt][2] = __float_as_uint(as[r0 + 4]);
                af[mt][3] = __float_as_uint(as[r0 + 8*AS_LD + 4]);
            }
            unsigned bf[8][2];
#pragma unroll
            for (int nt = 0; nt < 8; nt++) {
                int c0 = (k + qc)*BS_LD + wn*64 + nt*8 + qr;
                bf[nt][0] = __float_as_uint(bs[c0]);
                bf[nt][1] = __float_as_uint(bs[c0 + 4*BS_LD]);
            }
#pragma unroll
            for (int mt = 0; mt < 2; mt++)
#pragma unroll
                for (int nt = 0; nt < 8; nt++)
                    mma_tf32(acc[mt][nt], af[mt], bf[nt]);
        }
        if (kt + 1 < KT) {
            float* asw = As[cur ^ 1]; float* bsw = Bs[cur ^ 1];
            int sa = arow*AS_LD + acol;
            asw[sa+0]=f2tf(ra0.x); asw[sa+1]=f2tf(ra0.y); asw[sa+2]=f2tf(ra0.z); asw[sa+3]=f2tf(ra0.w);
            asw[sa+4]=f2tf(ra1.x); asw[sa+5]=f2tf(ra1.y); asw[sa+6]=f2tf(ra1.z); asw[sa+7]=f2tf(ra1.w);
            int sb = brow*BS_LD + bcol;
            bsw[sb+0]=f2tf(rb0.x); bsw[sb+1]=f2tf(rb0.y); bsw[sb+2]=f2tf(rb0.z); bsw[sb+3]=f2tf(rb0.w);
            bsw[sb+4]=f2tf(rb1.x); bsw[sb+5]=f2tf(rb1.y); bsw[sb+6]=f2tf(rb1.z); bsw[sb+7]=f2tf(rb1.w);
        }
        __syncthreads();
    }

    // epilogue
#pragma unroll
    for (int mt = 0; mt < 2; mt++) {
        int mA = m0 + wm*32 + mt*16 + qr;
        int mB = mA + 8;
#pragma unroll
        for (int nt = 0; nt < 8; nt++) {
            int n = n0 + wn*64 + nt*8 + qc*2;
            float b0 = bias[n], b1 = bias[n + 1];
            float v0 = acc[mt][nt][0] + b0;
            float v1 = acc[mt][nt][1] + b1;
            float v2 = acc[mt][nt][2] + b0;
            float v3 = acc[mt][nt][3] + b1;
            if (act) {
                v0 = v0 > 0.f ? v0 : expm1f(v0);
                v1 = v1 > 0.f ? v1 : expm1f(v1);
                v2 = v2 > 0.f ? v2 : expm1f(v2);
                v3 = v3 > 0.f ? v3 : expm1f(v3);
            }
            if (res) {
                const float* rA = res + (size_t)mA*N + n;
                const float* rB = res + (size_t)mB*N + n;
                v0 += rA[0]; v1 += rA[1];
                v2 += rB[0]; v3 += rB[1];
            }
            float2 oA; oA.x = v0; oA.y = v1;
            float2 oB; oB.x = v2; oB.y = v3;
            *(float2*)(C + (size_t)mA*N + n) = oA;
            *(float2*)(C + (size_t)mB*N + n) = oB;
        }
    }
}

// ---------------- e -> LN -> E proj, sigmoid(G proj) ----------------
__global__ void __launch_bounds__(256) eg_kernel(
    const float* __restrict__ e,
    const float* __restrict__ lng, const float* __restrict__ lnb,
    const float* __restrict__ WE, const float* __restrict__ bE,
    const float* __restrict__ WG, const float* __restrict__ bG)
{
    __shared__ float xs[64*65];
    __shared__ float wE[64*16], wG[64*16];
    __shared__ float ob[32*65];
    __shared__ float sg[64], sb[64], sbE[16], sbG[16];
    int t = threadIdx.x;
    size_t row0 = (size_t)blockIdx.x * 64;

    for (int i = t; i < 1024; i += 256) { wE[i] = WE[i]; wG[i] = WG[i]; }
    if (t < 64) { sg[t] = lng[t]; sb[t] = lnb[t]; }
    if (t < 16) { sbE[t] = bE[t]; sbG[t] = bG[t]; }
#pragma unroll
    for (int i = 0; i < 16; i++) {
        int idx = t + i*256;
        int r = idx >> 6, c = idx & 63;
        xs[r*65 + c] = e[row0*64 + idx];
    }
    __syncthreads();
    {
        int r = t >> 2, part = t & 3;
        float lv[16]; float s = 0.f;
#pragma unroll
        for (int k = 0; k < 16; k++) { lv[k] = xs[r*65 + part*16 + k]; s += lv[k]; }
        s += __shfl_xor_sync(0xffffffff, s, 1);
        s += __shfl_xor_sync(0xffffffff, s, 2);
        float mu = s * (1.0f/64.0f);
        float q = 0.f;
#pragma unroll
        for (int k = 0; k < 16; k++) { float d = lv[k]-mu; q += d*d; }
        q += __shfl_xor_sync(0xffffffff, q, 1);
        q += __shfl_xor_sync(0xffffffff, q, 2);
        float rsg = rsqrtf(q * (1.0f/64.0f) + 1e-5f);
#pragma unroll
        for (int k = 0; k < 16; k++) {
            int c = part*16 + k;
            xs[r*65 + c] = (lv[k]-mu)*rsg*sg[c] + sb[c];
        }
    }
    __syncthreads();
    {
        int o = t & 31, rg = t >> 5;
        bool isE = (o < 16);
        int oo = isE ? o : o - 16;
        const float* wp = isE ? wE : wG;
#pragma unroll
        for (int i = 0; i < 8; i++) {
            int rr = rg*8 + i;
            float a = 0.f;
#pragma unroll
            for (int k = 0; k < 64; k++) a += xs[rr*65 + k] * wp[k*16 + oo];
            a += isE ? sbE[oo] : sbG[oo];
            if (!isE) a = 1.0f / (1.0f + expf(-a));
            ob[o*65 + rr] = a;
        }
    }
    __syncthreads();
    int b_ = (int)(row0 >> 18);
    int rem = (int)(row0 & (NN - 1));
    int l = rem >> 9, m0 = rem & 511;
#pragma unroll
    for (int i = 0; i < 8; i++) {
        int idx = t + i*256;
        int o = idx >> 6, rr = idx & 63;
        float val = ob[o*65 + rr];
        int hd = o & 15;
        size_t dst = ((size_t)(b_*HEADS + hd))*NN + (size_t)l*512 + m0 + rr;
        if (o < 16) g_E[dst] = val; else g_gate[dst] = val;
    }
}

// ---------------- Q@K^T, scale, clip, +E -> H_hat ----------------
__global__ void __launch_bounds__(256) qk_kernel(const float* __restrict__ qkv)
{
    __shared__ float Qs[64*65];  // [d][l]
    __shared__ float Ks[64*65];  // [d][m]
    int t = threadIdx.x;
    int m0 = blockIdx.x * 64, l0 = blockIdx.y * 64;
    int z = blockIdx.z;
    int b = z >> 4, hd = z & 15;
    const float* qb = qkv + (size_t)b*NSEQ*3*NDIM + hd;
#pragma unroll
    for (int i = 0; i < 16; i++) {
        int idx = t + i*256;
        int d = idx & 63, r = idx >> 6;
        Qs[d*65 + r] = qb[(size_t)(l0 + r)*(3*NDIM) + d*16];
        Ks[d*65 + r] = qb[(size_t)(m0 + r)*(3*NDIM) + NDIM + d*16];
    }
    __syncthreads();
    int tx = t & 15, ty = t >> 4;
    float acc[4][4];
#pragma unroll
    for (int i = 0; i < 4; i++)
#pragma unroll
        for (int j = 0; j < 4; j++) acc[i][j] = 0.f;
#pragma unroll 4
    for (int d = 0; d < 64; d++) {
        float a[4], bb[4];
#pragma unroll
        for (int i = 0; i < 4; i++) a[i]  = Qs[d*65 + ty*4 + i];
#pragma unroll
        for (int j = 0; j < 4; j++) bb[j] = Ks[d*65 + tx*4 + j];
#pragma unroll
        for (int i = 0; i < 4; i++)
#pragma unroll
            for (int j = 0; j < 4; j++) acc[i][j] += a[i]*bb[j];
    }
    size_t base = (size_t)z * NN;
#pragma unroll
    for (int i = 0; i < 4; i++) {
        int l = l0 + ty*4 + i;
        size_t ro = base + (size_t)l*512 + m0 + tx*4;
        float4 ev = *(const float4*)&g_E[ro];
        float4 hv;
        hv.x = fminf(fmaxf(acc[i][0]*0.125f, -5.f), 5.f) + ev.x;
        hv.y = fminf(fmaxf(acc[i][1]*0.125f, -5.f), 5.f) + ev.y;
        hv.z = fminf(fmaxf(acc[i][2]*0.125f, -5.f), 5.f) + ev.z;
        hv.w = fminf(fmaxf(acc[i][3]*0.125f, -5.f), 5.f) + ev.w;
        *(float4*)&g_H[ro] = hv;
    }
}

// ---------------- softmax over m, * gates ----------------
__global__ void __launch_bounds__(256) softmax_kernel()
{
    int row = blockIdx.x;               // z*512 + l
    int t = threadIdx.x;
    size_t base = (size_t)row * 512;
    float v0 = g_H[base + t], v1 = g_H[base + 256 + t];
    __shared__ float red[8];
    int lane = t & 31, w = t >> 5;
    float mx = fmaxf(v0, v1);
#pragma unroll
    for (int o = 16; o; o >>= 1) mx = fmaxf(mx, __shfl_xor_sync(0xffffffff, mx, o));
    if (lane == 0) red[w] = mx;
    __syncthreads();
    float m = red[0];
#pragma unroll
    for (int i = 1; i < 8; i++) m = fmaxf(m, red[i]);
    __syncthreads();
    float e0 = expf(v0 - m), e1 = expf(v1 - m);
    float s = e0 + e1;
#pragma unroll
    for (int o = 16; o; o >>= 1) s += __shfl_xor_sync(0xffffffff, s, o);
    if (lane == 0) red[w] = s;
    __syncthreads();
    float tot = 0.f;
#pragma unroll
    for (int i = 0; i < 8; i++) tot += red[i];
    float inv = 1.0f / tot;
    g_At[base + t]       = e0 * inv * g_gate[base + t];
    g_At[base + 256 + t] = e1 * inv * g_gate[base + 256 + t];
}

// ---------------- A_tild @ V -> V_att (written in (b,l,k*16+h) layout) ----------------
__global__ void __launch_bounds__(256) av_kernel(const float* __restrict__ qkv)
{
    __shared__ float As[64*65]; // [m][l]
    __shared__ float Vs[64*64]; // [m][k]
    int t = threadIdx.x;
    int l0 = blockIdx.x * 64;
    int z = blockIdx.y;
    int b = z >> 4, hd = z & 15;
    int tx = t & 15, ty = t >> 4;
    const float* vb = qkv + (size_t)b*NSEQ*3*NDIM + 2*NDIM + hd;
    size_t abase = (size_t)z*NN + (size_t)l0*512;
    float acc[4][4];
#pragma unroll
    for (int i = 0; i < 4; i++)
#pragma unroll
        for (int j = 0; j < 4; j++) acc[i][j] = 0.f;

    for (int mt = 0; mt < 512; mt += 64) {
#pragma unroll
        for (int i = 0; i < 16; i++) {
            int idx = t + i*256;
            int c = idx & 63, r = idx >> 6;
            As[c*65 + r] = g_At[abase + (size_t)r*512 + mt + c];
            Vs[r*64 + c] = vb[(size_t)(mt + r)*(3*NDIM) + c*16];
        }
        __syncthreads();
#pragma unroll 4
        for (int m = 0; m < 64; m++) {
            float a[4], vv[4];
#pragma unroll
            for (int i = 0; i < 4; i++) a[i]  = As[m*65 + ty*4 + i];
#pragma unroll
            for (int j = 0; j < 4; j++) vv[j] = Vs[m*64 + tx*4 + j];
#pragma unroll
            for (int i = 0; i < 4; i++)
#pragma unroll
                for (int j = 0; j < 4; j++) acc[i][j] += a[i]*vv[j];
        }
        __syncthreads();
    }
#pragma unroll
    for (int i = 0; i < 4; i++) {
        int l = l0 + ty*4 + i;
#pragma unroll
        for (int j = 0; j < 4; j++) {
            int k = tx*4 + j;
            g_vatt[(size_t)(b*NSEQ + l)*NDIM + k*16 + hd] = acc[i][j];
        }
    }
}

// ---------------- fused e-out: H_hat@W_Oe + b + e -> LN -> FFN(64->128->64) -> +res ----------------
#define EOUT_SMEM_FLOATS 31360
__global__ void __launch_bounds__(256) eout_kernel(
    const float* __restrict__ e,
    const float* __restrict__ WOe, const float* __restrict__ bOe,
    const float* __restrict__ lng, const float* __restrict__ lnb,
    const float* __restrict__ W1, const float* __restrict__ b1,
    const float* __restrict__ W2, const float* __restrict__ b2,
    float* __restrict__ eout)
{
    extern __shared__ float sm[];
    float* W1s  = sm;              // 8192
    float* W2s  = W1s  + 8192;     // 8192
    float* WOes = W2s  + 8192;     // 1024
    float* xs   = WOes + 1024;     // 64*65 = 4160
    float* hs   = xs   + 4160;     // 64*129 = 8256
    float* Hsm  = hs   + 8256;     // 16*64 = 1024
    float* smu  = Hsm  + 1024;     // 64
    float* srs  = smu  + 64;       // 64
    float* sbOe = srs  + 64;       // 64
    float* sge  = sbOe + 64;       // 64
    float* sbe  = sge  + 64;       // 64
    float* sb1  = sbe  + 64;       // 128
    float* sb2  = sb1  + 128;      // 64  -> total 31360

    int t = threadIdx.x;
    size_t row0 = (size_t)blockIdx.x * 64;
    int b_ = (int)(row0 >> 18);
    int rem = (int)(row0 & (NN - 1));
    int l = rem >> 9, m0 = rem & 511;

    for (int i = t; i < 8192; i += 256) { W1s[i] = W1[i]; W2s[i] = W2[i]; }
    for (int i = t; i < 1024; i += 256) WOes[i] = WOe[i];
    if (t < 64) { sbOe[t] = bOe[t]; sge[t] = lng[t]; sbe[t] = lnb[t]; sb2[t] = b2[t]; }
    if (t < 128) sb1[t] = b1[t];
    for (int i = t; i < 1024; i += 256) {
        int hd = i >> 6, r = i & 63;
        Hsm[hd*64 + r] = g_H[((size_t)(b_*HEADS + hd))*NN + (size_t)l*512 + m0 + r];
    }
    __syncthreads();

    int tx = t & 15, ty = t >> 4;
    // Phase A: xs = H@WOe + bOe + e  (64 x 64)
    {
        float acc[4][4];
#pragma unroll
        for (int i = 0; i < 4; i++)
#pragma unroll
            for (int j = 0; j < 4; j++) acc[i][j] = 0.f;
#pragma unroll
        for (int hd = 0; hd < 16; hd++) {
            float a[4], w[4];
#pragma unroll
            for (int i = 0; i < 4; i++) a[i] = Hsm[hd*64 + ty*4 + i];
#pragma unroll
            for (int j = 0; j < 4; j++) w[j] = WOes[hd*64 + tx*4 + j];
#pragma unroll
            for (int i = 0; i < 4; i++)
#pragma unroll
                for (int j = 0; j < 4; j++) acc[i][j] += a[i]*w[j];
        }
#pragma unroll
        for (int i = 0; i < 4; i++) {
            int r = ty*4 + i;
            float4 ev = *(const float4*)&e[(row0 + r)*64 + tx*4];
            xs[r*65 + tx*4 + 0] = acc[i][0] + sbOe[tx*4+0] + ev.x;
            xs[r*65 + tx*4 + 1] = acc[i][1] + sbOe[tx*4+1] + ev.y;
            xs[r*65 + tx*4 + 2] = acc[i][2] + sbOe[tx*4+2] + ev.z;
            xs[r*65 + tx*4 + 3] = acc[i][3] + sbOe[tx*4+3] + ev.w;
        }
    }
    __syncthreads();
    // Phase B: LN stats per row
    {
        int r = t >> 2, part = t & 3;
        float lv[16]; float s = 0.f;
#pragma unroll
        for (int k = 0; k < 16; k++) { lv[k] = xs[r*65 + part*16 + k]; s += lv[k]; }
        s += __shfl_xor_sync(0xffffffff, s, 1);
        s += __shfl_xor_sync(0xffffffff, s, 2);
        float mu = s * (1.0f/64.0f);
        float q = 0.f;
#pragma unroll
        for (int k = 0; k < 16; k++) { float d = lv[k]-mu; q += d*d; }
        q += __shfl_xor_sync(0xffffffff, q, 1);
        q += __shfl_xor_sync(0xffffffff, q, 2);
        if (part == 0) { smu[r] = mu; srs[r] = rsqrtf(q*(1.0f/64.0f) + 1e-5f); }
    }
    __syncthreads();
    // Phase C: hidden = elu( LN(xs) @ W1 + b1 )  (64 x 128)
    {
        float acc[4][8];
#pragma unroll
        for (int i = 0; i < 4; i++)
#pragma unroll
            for (int j = 0; j < 8; j++) acc[i][j] = 0.f;
        float mur[4], rsr[4];
#pragma unroll
        for (int i = 0; i < 4; i++) { mur[i] = smu[ty*4+i]; rsr[i] = srs[ty*4+i]; }
#pragma unroll 4
        for (int k = 0; k < 64; k++) {
            float gk = sge[k], bk = sbe[k];
            float xn[4];
#pragma unroll
            for (int i = 0; i < 4; i++)
                xn[i] = (xs[(ty*4+i)*65 + k] - mur[i]) * rsr[i] * gk + bk;
            float w[8];
            *(float4*)&w[0] = *(float4*)&W1s[k*128 + tx*8];
            *(float4*)&w[4] = *(float4*)&W1s[k*128 + tx*8 + 4];
#pragma unroll
            for (int i = 0; i < 4; i++)
#pragma unroll
                for (int j = 0; j < 8; j++) acc[i][j] += xn[i]*w[j];
        }
#pragma unroll
        for (int i = 0; i < 4; i++)
#pragma unroll
            for (int j = 0; j < 8; j++) {
                float v = acc[i][j] + sb1[tx*8 + j];
                v = v > 0.f ? v : expm1f(v);
                hs[(ty*4+i)*129 + tx*8 + j] = v;
            }
    }
    __syncthreads();
    // Phase E: out = hs @ W2 + b2 + xs(residual)
    {
        float acc[4][4];
#pragma unroll
        for (int i = 0; i < 4; i++)
#pragma unroll
            for (int j = 0; j < 4; j++) acc[i][j] = 0.f;
#pragma unroll 4
        for (int j2 = 0; j2 < 128; j2++) {
            float hv[4], w[4];
#pragma unroll
            for (int i = 0; i < 4; i++) hv[i] = hs[(ty*4+i)*129 + j2];
            *(float4*)&w[0] = *(float4*)&W2s[j2*64 + tx*4];
#pragma unroll
            for (int i = 0; i < 4; i++)
#pragma unroll
                for (int j = 0; j < 4; j++) acc[i][j] += hv[i]*w[j];
        }
#pragma unroll
        for (int i = 0; i < 4; i++) {
            int r = ty*4 + i;
            int c = tx*4;
            float4 ov;
            ov.x = acc[i][0] + sb2[c+0] + xs[r*65 + c+0];
            ov.y = acc[i][1] + sb2[c+1] + xs[r*65 + c+1];
            ov.z = acc[i][2] + sb2[c+2] + xs[r*65 + c+2];
            ov.w = acc[i][3] + sb2[c+3] + xs[r*65 + c+3];
            *(float4*)&eout[(row0 + r)*64 + c] = ov;
        }
    }
}

// ---------------- host launcher ----------------
extern "C" void kernel_launch(void* const* d_in, const int* in_sizes, int n_in,
                              void* d_out, int out_size)
{
    const float* h        = (const float*)d_in[0];
    const float* e        = (const float*)d_in[1];
    const float* ln_h_g   = (const float*)d_in[2];
    const float* ln_h_b   = (const float*)d_in[3];
    const float* ln_e_g   = (const float*)d_in[4];
    const float* ln_e_b   = (const float*)d_in[5];
    const float* W_E      = (const float*)d_in[6];
    const float* b_E      = (const float*)d_in[7];
    const float* W_QKV    = (const float*)d_in[8];
    const float* b_QKV    = (const float*)d_in[9];
    const float* W_G      = (const float*)d_in[10];
    const float* b_G      = (const float*)d_in[11];
    const float* W_Oh     = (const float*)d_in[12];
    const float* b_Oh     = (const float*)d_in[13];
    const float* ffn_ln_h_g = (const float*)d_in[14];
    const float* ffn_ln_h_b = (const float*)d_in[15];
    const float* W_h1     = (const float*)d_in[16];
    const float* b_h1     = (const float*)d_in[17];
    const float* W_h2     = (const float*)d_in[18];
    const float* b_h2     = (const float*)d_in[19];
    const float* W_Oe     = (const float*)d_in[20];
    const float* b_Oe     = (const float*)d_in[21];
    const float* ffn_ln_e_g = (const float*)d_in[22];
    const float* ffn_ln_e_b = (const float*)d_in[23];
    const float* W_e1     = (const float*)d_in[24];
    const float* b_e1     = (const float*)d_in[25];
    const float* W_e2     = (const float*)d_in[26];
    const float* b_e2     = (const float*)d_in[27];

    float* out_h = (float*)d_out;
    float* out_e = out_h + H_OUT_ELEMS;

    float *p_hln, *p_qkv, *p_vatt, *p_h1, *p_h2, *p_act;
    cudaGetSymbolAddress((void**)&p_hln,  g_hln);
    cudaGetSymbolAddress((void**)&p_qkv,  g_qkv);
    cudaGetSymbolAddress((void**)&p_vatt, g_vatt);
    cudaGetSymbolAddress((void**)&p_h1,   g_h1);
    cudaGetSymbolAddress((void**)&p_h2,   g_h2);
    cudaGetSymbolAddress((void**)&p_act,  g_act);

    // h path pre-attention
    ln1024_kernel<<<BN, 256>>>(h, ln_h_g, ln_h_b, p_hln);
    gemm_tc_kernel<<<dim3(3*NDIM/128, BN/128), 256>>>(p_hln, W_QKV, b_QKV, nullptr, p_qkv,
                                                      BN, 3*NDIM, NDIM, 0);
    // e path: LN + E/G projections
    eg_kernel<<<(unsigned)(EROWS/64), 256>>>(e, ln_e_g, ln_e_b, W_E, b_E, W_G, b_G);
    // attention
    qk_kernel<<<dim3(8, 8, BHN), 256>>>(p_qkv);
    softmax_kernel<<<BHN*NSEQ, 256>>>();
    av_kernel<<<dim3(8, BHN), 256>>>(p_qkv);
    // h path post-attention
    gemm_tc_kernel<<<dim3(NDIM/128, BN/128), 256>>>(p_vatt, W_Oh, b_Oh, h, p_h1,
                                                    BN, NDIM, NDIM, 0);
    ln1024_kernel<<<BN, 256>>>(p_h1, ffn_ln_h_g, ffn_ln_h_b, p_h2);
    gemm_tc_kernel<<<dim3(FFN_H/128, BN/128), 256>>>(p_h2, W_h1, b_h1, nullptr, p_act,
                                                     BN, FFN_H, NDIM, 1);
    gemm_tc_kernel<<<dim3(NDIM/128, BN/128), 256>>>(p_act, W_h2, b_h2, p_h1, out_h,
                                                    BN, NDIM, FFN_H, 0);
    // fused e output path
    cudaFuncSetAttribute(eout_kernel, cudaFuncAttributeMaxDynamicSharedMemorySize,
                         EOUT_SMEM_FLOATS * 4);
    eout_kernel<<<(unsigned)(EROWS/64), 256, EOUT_SMEM_FLOATS * 4>>>(
        e, W_Oe, b_Oe, ffn_ln_e_g, ffn_ln_e_b, W_e1, b_e1, W_e2, b_e2, out_e);
}

// round 3
// speedup vs baseline: 1.7169x; 1.7169x over previous
#include <cuda_runtime.h>
#include <cuda_bf16.h>
#include <math.h>

// ---------------- problem constants ----------------
#define BATCH   4
#define NSEQ    512
#define NDIM    1024
#define EDIM    64
#define HEADS   16
#define DOTD    64
#define FFN_H   2048
#define FFN_E   128
#define BN      (BATCH*NSEQ)          // 2048 token rows
#define NN      (NSEQ*NSEQ)           // 262144 per batch
#define BHN     (BATCH*HEADS)         // 64
#define EROWS   ((size_t)BATCH*NSEQ*NSEQ) // 1048576 edge rows
#define H_OUT_ELEMS (BN*NDIM)         // 2097152

// ---------------- scratch (device globals; no allocs allowed) ----------------
__device__ float g_hln [BN*NDIM];
__device__ float g_qkv [BN*3*NDIM];
__device__ float g_E   [(size_t)BHN*NN];   // (b*16+h, l*512+m)
__device__ float g_gate[(size_t)BHN*NN];
__device__ float g_H   [(size_t)BHN*NN];   // H_hat = clip(A)+E
__device__ float g_At  [(size_t)BHN*NN];   // softmax*gates
__device__ float g_vatt[BN*NDIM];
__device__ float g_h1  [BN*NDIM];          // h after O_h + residual
__device__ float g_h2  [BN*NDIM];          // LN of g_h1
__device__ float g_act [BN*FFN_H];

// ---------------- LayerNorm over 1024 ----------------
__global__ void __launch_bounds__(256) ln1024_kernel(
    const float* __restrict__ x, const float* __restrict__ g,
    const float* __restrict__ b, float* __restrict__ y)
{
    int row = blockIdx.x, t = threadIdx.x;
    const float* xr = x + (size_t)row * NDIM;
    float v[4]; float s = 0.f;
#pragma unroll
    for (int i = 0; i < 4; i++) { v[i] = xr[t + i*256]; s += v[i]; }
    __shared__ float red[8];
    int lane = t & 31, w = t >> 5;
#pragma unroll
    for (int o = 16; o; o >>= 1) s += __shfl_xor_sync(0xffffffff, s, o);
    if (lane == 0) red[w] = s;
    __syncthreads();
    float tot = 0.f;
#pragma unroll
    for (int i = 0; i < 8; i++) tot += red[i];
    float mu = tot * (1.0f/NDIM);
    __syncthreads();
    float q = 0.f;
#pragma unroll
    for (int i = 0; i < 4; i++) { float d = v[i]-mu; q += d*d; }
#pragma unroll
    for (int o = 16; o; o >>= 1) q += __shfl_xor_sync(0xffffffff, q, o);
    if (lane == 0) red[w] = q;
    __syncthreads();
    float qt = 0.f;
#pragma unroll
    for (int i = 0; i < 8; i++) qt += red[i];
    float rs = rsqrtf(qt * (1.0f/NDIM) + 1e-5f);
    float* yr = y + (size_t)row * NDIM;
#pragma unroll
    for (int i = 0; i < 4; i++) {
        int c = t + i*256;
        yr[c] = (v[i]-mu)*rs*g[c] + b[c];
    }
}

// ---------------- tf32 helpers ----------------
__device__ __forceinline__ float f2tf(float x) {
    unsigned r;
    asm("cvt.rna.tf32.f32 %0, %1;" : "=r"(r) : "f"(x));
    return __uint_as_float(r);
}

__device__ __forceinline__ void mma_tf32(float* c, const unsigned* a, const unsigned* b) {
    asm volatile(
        "mma.sync.aligned.m16n8k8.row.col.f32.tf32.tf32.f32 "
        "{%0,%1,%2,%3}, {%4,%5,%6,%7}, {%8,%9}, {%0,%1,%2,%3};\n"
        : "+f"(c[0]), "+f"(c[1]), "+f"(c[2]), "+f"(c[3])
        : "r"(a[0]), "r"(a[1]), "r"(a[2]), "r"(a[3]), "r"(b[0]), "r"(b[1]));
}

// ---------------- tf32 tensor-core GEMM: C = act(A@W + bias) (+res) ----------------
// 128x128 tile, BK=16, 256 threads (8 warps), warp tile 32x64.
#define AS_LD 17
#define BS_LD 132
__global__ void __launch_bounds__(256) gemm_tc_kernel(
    const float* __restrict__ A, const float* __restrict__ W,
    const float* __restrict__ bias, const float* __restrict__ res,
    float* __restrict__ C, int M, int N, int K, int act)
{
    __shared__ float As[2][128*AS_LD];
    __shared__ float Bs[2][16*BS_LD];

    int t = threadIdx.x;
    int lane = t & 31;
    int w = t >> 5;
    int wm = w & 3;            // 4 m-tiles of 32 rows
    int wn = w >> 2;           // 2 n-tiles of 64 cols
    int qr = lane >> 2;        // 0..7
    int qc = lane & 3;         // 0..3
    int n0 = blockIdx.x * 128, m0 = blockIdx.y * 128;

    int arow = t >> 1;             // 0..127
    int acol = (t & 1) * 8;        // 0 or 8
    int brow = t >> 4;             // 0..15
    int bcol = (t & 15) * 8;       // 0..120

    const float* Aptr = A + (size_t)(m0 + arow)*K + acol;
    const float* Bptr = W + (size_t)brow*N + n0 + bcol;

    float acc[2][8][4];
#pragma unroll
    for (int i = 0; i < 2; i++)
#pragma unroll
        for (int j = 0; j < 8; j++)
#pragma unroll
            for (int k = 0; k < 4; k++) acc[i][j][k] = 0.f;

    int KT = K / 16;
    float4 ra0, ra1, rb0, rb1;
    ra0 = *(const float4*)(Aptr + 0);
    ra1 = *(const float4*)(Aptr + 4);
    rb0 = *(const float4*)(Bptr + 0);
    rb1 = *(const float4*)(Bptr + 4);
    {
        float* as = As[0]; float* bs = Bs[0];
        int sa = arow*AS_LD + acol;
        as[sa+0]=f2tf(ra0.x); as[sa+1]=f2tf(ra0.y); as[sa+2]=f2tf(ra0.z); as[sa+3]=f2tf(ra0.w);
        as[sa+4]=f2tf(ra1.x); as[sa+5]=f2tf(ra1.y); as[sa+6]=f2tf(ra1.z); as[sa+7]=f2tf(ra1.w);
        int sb = brow*BS_LD + bcol;
        bs[sb+0]=f2tf(rb0.x); bs[sb+1]=f2tf(rb0.y); bs[sb+2]=f2tf(rb0.z); bs[sb+3]=f2tf(rb0.w);
        bs[sb+4]=f2tf(rb1.x); bs[sb+5]=f2tf(rb1.y); bs[sb+6]=f2tf(rb1.z); bs[sb+7]=f2tf(rb1.w);
    }
    __syncthreads();

    for (int kt = 0; kt < KT; kt++) {
        int cur = kt & 1;
        if (kt + 1 < KT) {
            int k0 = (kt + 1) * 16;
            ra0 = *(const float4*)(Aptr + k0);
            ra1 = *(const float4*)(Aptr + k0 + 4);
            rb0 = *(const float4*)(Bptr + (size_t)k0*N);
            rb1 = *(const float4*)(Bptr + (size_t)k0*N + 4);
        }
        const float* as = As[cur];
        const float* bs = Bs[cur];
#pragma unroll
        for (int ks = 0; ks < 2; ks++) {
            int k = ks * 8;
            unsigned af[2][4];
#pragma unroll
            for (int mt = 0; mt < 2; mt++) {
                int r0 = (wm*32 + mt*16 + qr) * AS_LD + k + qc;
                af[mt][0] = __float_as_uint(as[r0]);
                af[mt][1] = __float_as_uint(as[r0 + 8*AS_LD]);
                af[mt][2] = __float_as_uint(as[r0 + 4]);
                af[mt][3] = __float_as_uint(as[r0 + 8*AS_LD + 4]);
            }
            unsigned bf[8][2];
#pragma unroll
            for (int nt = 0; nt < 8; nt++) {
                int c0 = (k + qc)*BS_LD + wn*64 + nt*8 + qr;
                bf[nt][0] = __float_as_uint(bs[c0]);
                bf[nt][1] = __float_as_uint(bs[c0 + 4*BS_LD]);
            }
#pragma unroll
            for (int mt = 0; mt < 2; mt++)
#pragma unroll
                for (int nt = 0; nt < 8; nt++)
                    mma_tf32(acc[mt][nt], af[mt], bf[nt]);
        }
        if (kt + 1 < KT) {
            float* asw = As[cur ^ 1]; float* bsw = Bs[cur ^ 1];
            int sa = arow*AS_LD + acol;
            asw[sa+0]=f2tf(ra0.x); asw[sa+1]=f2tf(ra0.y); asw[sa+2]=f2tf(ra0.z); asw[sa+3]=f2tf(ra0.w);
            asw[sa+4]=f2tf(ra1.x); asw[sa+5]=f2tf(ra1.y); asw[sa+6]=f2tf(ra1.z); asw[sa+7]=f2tf(ra1.w);
            int sb = brow*BS_LD + bcol;
            bsw[sb+0]=f2tf(rb0.x); bsw[sb+1]=f2tf(rb0.y); bsw[sb+2]=f2tf(rb0.z); bsw[sb+3]=f2tf(rb0.w);
            bsw[sb+4]=f2tf(rb1.x); bsw[sb+5]=f2tf(rb1.y); bsw[sb+6]=f2tf(rb1.z); bsw[sb+7]=f2tf(rb1.w);
        }
        __syncthreads();
    }

    // epilogue
#pragma unroll
    for (int mt = 0; mt < 2; mt++) {
        int mA = m0 + wm*32 + mt*16 + qr;
        int mB = mA + 8;
#pragma unroll
        for (int nt = 0; nt < 8; nt++) {
            int n = n0 + wn*64 + nt*8 + qc*2;
            float b0 = bias[n], b1 = bias[n + 1];
            float v0 = acc[mt][nt][0] + b0;
            float v1 = acc[mt][nt][1] + b1;
            float v2 = acc[mt][nt][2] + b0;
            float v3 = acc[mt][nt][3] + b1;
            if (act) {
                v0 = v0 > 0.f ? v0 : expm1f(v0);
                v1 = v1 > 0.f ? v1 : expm1f(v1);
                v2 = v2 > 0.f ? v2 : expm1f(v2);
                v3 = v3 > 0.f ? v3 : expm1f(v3);
            }
            if (res) {
                const float* rA = res + (size_t)mA*N + n;
                const float* rB = res + (size_t)mB*N + n;
                v0 += rA[0]; v1 += rA[1];
                v2 += rB[0]; v3 += rB[1];
            }
            float2 oA; oA.x = v0; oA.y = v1;
            float2 oB; oB.x = v2; oB.y = v3;
            *(float2*)(C + (size_t)mA*N + n) = oA;
            *(float2*)(C + (size_t)mB*N + n) = oB;
        }
    }
}

// ---------------- e -> LN -> E proj, sigmoid(G proj) ----------------
__global__ void __launch_bounds__(256) eg_kernel(
    const float* __restrict__ e,
    const float* __restrict__ lng, const float* __restrict__ lnb,
    const float* __restrict__ WE, const float* __restrict__ bE,
    const float* __restrict__ WG, const float* __restrict__ bG)
{
    __shared__ float xs[64*65];
    __shared__ float wE[64*16], wG[64*16];
    __shared__ float ob[32*65];
    __shared__ float sg[64], sb[64], sbE[16], sbG[16];
    int t = threadIdx.x;
    size_t row0 = (size_t)blockIdx.x * 64;

    for (int i = t; i < 1024; i += 256) { wE[i] = WE[i]; wG[i] = WG[i]; }
    if (t < 64) { sg[t] = lng[t]; sb[t] = lnb[t]; }
    if (t < 16) { sbE[t] = bE[t]; sbG[t] = bG[t]; }
#pragma unroll
    for (int i = 0; i < 16; i++) {
        int idx = t + i*256;
        int r = idx >> 6, c = idx & 63;
        xs[r*65 + c] = e[row0*64 + idx];
    }
    __syncthreads();
    {
        int r = t >> 2, part = t & 3;
        float lv[16]; float s = 0.f;
#pragma unroll
        for (int k = 0; k < 16; k++) { lv[k] = xs[r*65 + part*16 + k]; s += lv[k]; }
        s += __shfl_xor_sync(0xffffffff, s, 1);
        s += __shfl_xor_sync(0xffffffff, s, 2);
        float mu = s * (1.0f/64.0f);
        float q = 0.f;
#pragma unroll
        for (int k = 0; k < 16; k++) { float d = lv[k]-mu; q += d*d; }
        q += __shfl_xor_sync(0xffffffff, q, 1);
        q += __shfl_xor_sync(0xffffffff, q, 2);
        float rsg = rsqrtf(q * (1.0f/64.0f) + 1e-5f);
#pragma unroll
        for (int k = 0; k < 16; k++) {
            int c = part*16 + k;
            xs[r*65 + c] = (lv[k]-mu)*rsg*sg[c] + sb[c];
        }
    }
    __syncthreads();
    {
        int o = t & 31, rg = t >> 5;
        bool isE = (o < 16);
        int oo = isE ? o : o - 16;
        const float* wp = isE ? wE : wG;
#pragma unroll
        for (int i = 0; i < 8; i++) {
            int rr = rg*8 + i;
            float a = 0.f;
#pragma unroll
            for (int k = 0; k < 64; k++) a += xs[rr*65 + k] * wp[k*16 + oo];
            a += isE ? sbE[oo] : sbG[oo];
            if (!isE) a = 1.0f / (1.0f + expf(-a));
            ob[o*65 + rr] = a;
        }
    }
    __syncthreads();
    int b_ = (int)(row0 >> 18);
    int rem = (int)(row0 & (NN - 1));
    int l = rem >> 9, m0 = rem & 511;
#pragma unroll
    for (int i = 0; i < 8; i++) {
        int idx = t + i*256;
        int o = idx >> 6, rr = idx & 63;
        float val = ob[o*65 + rr];
        int hd = o & 15;
        size_t dst = ((size_t)(b_*HEADS + hd))*NN + (size_t)l*512 + m0 + rr;
        if (o < 16) g_E[dst] = val; else g_gate[dst] = val;
    }
}

// ---------------- Q@K^T, scale, clip, +E -> H_hat ----------------
__global__ void __launch_bounds__(256) qk_kernel(const float* __restrict__ qkv)
{
    __shared__ float Qs[64*65];  // [d][l]
    __shared__ float Ks[64*65];  // [d][m]
    int t = threadIdx.x;
    int m0 = blockIdx.x * 64, l0 = blockIdx.y * 64;
    int z = blockIdx.z;
    int b = z >> 4, hd = z & 15;
    const float* qb = qkv + (size_t)b*NSEQ*3*NDIM + hd;
#pragma unroll
    for (int i = 0; i < 16; i++) {
        int idx = t + i*256;
        int d = idx & 63, r = idx >> 6;
        Qs[d*65 + r] = qb[(size_t)(l0 + r)*(3*NDIM) + d*16];
        Ks[d*65 + r] = qb[(size_t)(m0 + r)*(3*NDIM) + NDIM + d*16];
    }
    __syncthreads();
    int tx = t & 15, ty = t >> 4;
    float acc[4][4];
#pragma unroll
    for (int i = 0; i < 4; i++)
#pragma unroll
        for (int j = 0; j < 4; j++) acc[i][j] = 0.f;
#pragma unroll 4
    for (int d = 0; d < 64; d++) {
        float a[4], bb[4];
#pragma unroll
        for (int i = 0; i < 4; i++) a[i]  = Qs[d*65 + ty*4 + i];
#pragma unroll
        for (int j = 0; j < 4; j++) bb[j] = Ks[d*65 + tx*4 + j];
#pragma unroll
        for (int i = 0; i < 4; i++)
#pragma unroll
            for (int j = 0; j < 4; j++) acc[i][j] += a[i]*bb[j];
    }
    size_t base = (size_t)z * NN;
#pragma unroll
    for (int i = 0; i < 4; i++) {
        int l = l0 + ty*4 + i;
        size_t ro = base + (size_t)l*512 + m0 + tx*4;
        float4 ev = *(const float4*)&g_E[ro];
        float4 hv;
        hv.x = fminf(fmaxf(acc[i][0]*0.125f, -5.f), 5.f) + ev.x;
        hv.y = fminf(fmaxf(acc[i][1]*0.125f, -5.f), 5.f) + ev.y;
        hv.z = fminf(fmaxf(acc[i][2]*0.125f, -5.f), 5.f) + ev.z;
        hv.w = fminf(fmaxf(acc[i][3]*0.125f, -5.f), 5.f) + ev.w;
        *(float4*)&g_H[ro] = hv;
    }
}

// ---------------- softmax over m, * gates ----------------
__global__ void __launch_bounds__(256) softmax_kernel()
{
    int row = blockIdx.x;               // z*512 + l
    int t = threadIdx.x;
    size_t base = (size_t)row * 512;
    float v0 = g_H[base + t], v1 = g_H[base + 256 + t];
    __shared__ float red[8];
    int lane = t & 31, w = t >> 5;
    float mx = fmaxf(v0, v1);
#pragma unroll
    for (int o = 16; o; o >>= 1) mx = fmaxf(mx, __shfl_xor_sync(0xffffffff, mx, o));
    if (lane == 0) red[w] = mx;
    __syncthreads();
    float m = red[0];
#pragma unroll
    for (int i = 1; i < 8; i++) m = fmaxf(m, red[i]);
    __syncthreads();
    float e0 = expf(v0 - m), e1 = expf(v1 - m);
    float s = e0 + e1;
#pragma unroll
    for (int o = 16; o; o >>= 1) s += __shfl_xor_sync(0xffffffff, s, o);
    if (lane == 0) red[w] = s;
    __syncthreads();
    float tot = 0.f;
#pragma unroll
    for (int i = 0; i < 8; i++) tot += red[i];
    float inv = 1.0f / tot;
    g_At[base + t]       = e0 * inv * g_gate[base + t];
    g_At[base + 256 + t] = e1 * inv * g_gate[base + 256 + t];
}

// ---------------- A_tild @ V -> V_att (written in (b,l,k*16+h) layout) ----------------
__global__ void __launch_bounds__(256) av_kernel(const float* __restrict__ qkv)
{
    __shared__ float As[64*65]; // [m][l]
    __shared__ float Vs[64*64]; // [m][k]
    int t = threadIdx.x;
    int l0 = blockIdx.x * 64;
    int z = blockIdx.y;
    int b = z >> 4, hd = z & 15;
    int tx = t & 15, ty = t >> 4;
    const float* vb = qkv + (size_t)b*NSEQ*3*NDIM + 2*NDIM + hd;
    size_t abase = (size_t)z*NN + (size_t)l0*512;
    float acc[4][4];
#pragma unroll
    for (int i = 0; i < 4; i++)
#pragma unroll
        for (int j = 0; j < 4; j++) acc[i][j] = 0.f;

    for (int mt = 0; mt < 512; mt += 64) {
#pragma unroll
        for (int i = 0; i < 16; i++) {
            int idx = t + i*256;
            int c = idx & 63, r = idx >> 6;
            As[c*65 + r] = g_At[abase + (size_t)r*512 + mt + c];
            Vs[r*64 + c] = vb[(size_t)(mt + r)*(3*NDIM) + c*16];
        }
        __syncthreads();
#pragma unroll 4
        for (int m = 0; m < 64; m++) {
            float a[4], vv[4];
#pragma unroll
            for (int i = 0; i < 4; i++) a[i]  = As[m*65 + ty*4 + i];
#pragma unroll
            for (int j = 0; j < 4; j++) vv[j] = Vs[m*64 + tx*4 + j];
#pragma unroll
            for (int i = 0; i < 4; i++)
#pragma unroll
                for (int j = 0; j < 4; j++) acc[i][j] += a[i]*vv[j];
        }
        __syncthreads();
    }
#pragma unroll
    for (int i = 0; i < 4; i++) {
        int l = l0 + ty*4 + i;
#pragma unroll
        for (int j = 0; j < 4; j++) {
            int k = tx*4 + j;
            g_vatt[(size_t)(b*NSEQ + l)*NDIM + k*16 + hd] = acc[i][j];
        }
    }
}

// ---------------- fused e-out: H_hat@W_Oe + b + e -> LN -> FFN(64->128->64) -> +res ----------------
// 512 threads, 128 edge rows per block.
#define EOUT_SMEM_FLOATS 44928
__global__ void __launch_bounds__(512) eout_kernel(
    const float* __restrict__ e,
    const float* __restrict__ WOe, const float* __restrict__ bOe,
    const float* __restrict__ lng, const float* __restrict__ lnb,
    const float* __restrict__ W1, const float* __restrict__ b1,
    const float* __restrict__ W2, const float* __restrict__ b2,
    float* __restrict__ eout)
{
    extern __shared__ float sm[];
    float* W1s  = sm;              // 8192
    float* W2s  = W1s  + 8192;     // 8192
    float* WOes = W2s  + 8192;     // 1024
    float* xs   = WOes + 1024;     // 128*65 = 8320
    float* hs   = xs   + 8320;     // 128*129 = 16512
    float* Hsm  = hs   + 16512;    // 16*128 = 2048
    float* smu  = Hsm  + 2048;     // 128
    float* srs  = smu  + 128;      // 128
    float* sbOe = srs  + 128;      // 64
    float* sge  = sbOe + 64;       // 64
    float* sbe  = sge  + 64;       // 64
    float* sb1  = sbe  + 64;       // 128
    float* sb2  = sb1  + 128;      // 64  -> total 44928

    int t = threadIdx.x;
    size_t row0 = (size_t)blockIdx.x * 128;
    int b_ = (int)(row0 >> 18);
    int rem = (int)(row0 & (NN - 1));
    int l = rem >> 9, m0 = rem & 511;

    for (int i = t; i < 8192; i += 512) { W1s[i] = W1[i]; W2s[i] = W2[i]; }
    for (int i = t; i < 1024; i += 512) WOes[i] = WOe[i];
    if (t < 64) { sbOe[t] = bOe[t]; sge[t] = lng[t]; sbe[t] = lnb[t]; sb2[t] = b2[t]; }
    if (t >= 64 && t < 192) sb1[t - 64] = b1[t - 64];
    for (int i = t; i < 2048; i += 512) {
        int hd = i >> 7, r = i & 127;
        Hsm[hd*128 + r] = g_H[((size_t)(b_*HEADS + hd))*NN + (size_t)l*512 + m0 + r];
    }
    __syncthreads();

    int u = t >> 8;              // half: rows [u*64, u*64+64)
    int tt = t & 255;
    int tx = tt & 15, ty = tt >> 4;
    int rbase = u * 64;

    // Phase A: xs = H@WOe + bOe + e  (128 x 64)
    {
        float acc[4][4];
#pragma unroll
        for (int i = 0; i < 4; i++)
#pragma unroll
            for (int j = 0; j < 4; j++) acc[i][j] = 0.f;
#pragma unroll
        for (int hd = 0; hd < 16; hd++) {
            float a[4], w[4];
#pragma unroll
            for (int i = 0; i < 4; i++) a[i] = Hsm[hd*128 + rbase + ty*4 + i];
#pragma unroll
            for (int j = 0; j < 4; j++) w[j] = WOes[hd*64 + tx*4 + j];
#pragma unroll
            for (int i = 0; i < 4; i++)
#pragma unroll
                for (int j = 0; j < 4; j++) acc[i][j] += a[i]*w[j];
        }
#pragma unroll
        for (int i = 0; i < 4; i++) {
            int r = rbase + ty*4 + i;
            float4 ev = *(const float4*)&e[(row0 + r)*64 + tx*4];
            xs[r*65 + tx*4 + 0] = acc[i][0] + sbOe[tx*4+0] + ev.x;
            xs[r*65 + tx*4 + 1] = acc[i][1] + sbOe[tx*4+1] + ev.y;
            xs[r*65 + tx*4 + 2] = acc[i][2] + sbOe[tx*4+2] + ev.z;
            xs[r*65 + tx*4 + 3] = acc[i][3] + sbOe[tx*4+3] + ev.w;
        }
    }
    __syncthreads();
    // Phase B: LN stats per row (512 threads cover 128 rows x 4 parts)
    {
        int r = t >> 2, part = t & 3;
        float lv[16]; float s = 0.f;
#pragma unroll
        for (int k = 0; k < 16; k++) { lv[k] = xs[r*65 + part*16 + k]; s += lv[k]; }
        s += __shfl_xor_sync(0xffffffff, s, 1);
        s += __shfl_xor_sync(0xffffffff, s, 2);
        float mu = s * (1.0f/64.0f);
        float q = 0.f;
#pragma unroll
        for (int k = 0; k < 16; k++) { float d = lv[k]-mu; q += d*d; }
        q += __shfl_xor_sync(0xffffffff, q, 1);
        q += __shfl_xor_sync(0xffffffff, q, 2);
        if (part == 0) { smu[r] = mu; srs[r] = rsqrtf(q*(1.0f/64.0f) + 1e-5f); }
    }
    __syncthreads();
    // Phase C: hidden = elu( LN(xs) @ W1 + b1 )  (128 x 128)
    {
        float acc[4][8];
#pragma unroll
        for (int i = 0; i < 4; i++)
#pragma unroll
            for (int j = 0; j < 8; j++) acc[i][j] = 0.f;
        float mur[4], rsr[4];
#pragma unroll
        for (int i = 0; i < 4; i++) { mur[i] = smu[rbase + ty*4+i]; rsr[i] = srs[rbase + ty*4+i]; }
#pragma unroll 4
        for (int k = 0; k < 64; k++) {
            float gk = sge[k], bk = sbe[k];
            float xn[4];
#pragma unroll
            for (int i = 0; i < 4; i++)
                xn[i] = (xs[(rbase + ty*4+i)*65 + k] - mur[i]) * rsr[i] * gk + bk;
            float w[8];
            *(float4*)&w[0] = *(float4*)&W1s[k*128 + tx*8];
            *(float4*)&w[4] = *(float4*)&W1s[k*128 + tx*8 + 4];
#pragma unroll
            for (int i = 0; i < 4; i++)
#pragma unroll
                for (int j = 0; j < 8; j++) acc[i][j] += xn[i]*w[j];
        }
#pragma unroll
        for (int i = 0; i < 4; i++)
#pragma unroll
            for (int j = 0; j < 8; j++) {
                float v = acc[i][j] + sb1[tx*8 + j];
                v = v > 0.f ? v : expm1f(v);
                hs[(rbase + ty*4+i)*129 + tx*8 + j] = v;
            }
    }
    __syncthreads();
    // Phase E: out = hs @ W2 + b2 + xs(residual)
    {
        float acc[4][4];
#pragma unroll
        for (int i = 0; i < 4; i++)
#pragma unroll
            for (int j = 0; j < 4; j++) acc[i][j] = 0.f;
#pragma unroll 4
        for (int j2 = 0; j2 < 128; j2++) {
            float hv[4], w[4];
#pragma unroll
            for (int i = 0; i < 4; i++) hv[i] = hs[(rbase + ty*4+i)*129 + j2];
            *(float4*)&w[0] = *(float4*)&W2s[j2*64 + tx*4];
#pragma unroll
            for (int i = 0; i < 4; i++)
#pragma unroll
                for (int j = 0; j < 4; j++) acc[i][j] += hv[i]*w[j];
        }
#pragma unroll
        for (int i = 0; i < 4; i++) {
            int r = rbase + ty*4 + i;
            int c = tx*4;
            float4 ov;
            ov.x = acc[i][0] + sb2[c+0] + xs[r*65 + c+0];
            ov.y = acc[i][1] + sb2[c+1] + xs[r*65 + c+1];
            ov.z = acc[i][2] + sb2[c+2] + xs[r*65 + c+2];
            ov.w = acc[i][3] + sb2[c+3] + xs[r*65 + c+3];
            *(float4*)&eout[(row0 + r)*64 + c] = ov;
        }
    }
}

// ---------------- host launcher ----------------
extern "C" void kernel_launch(void* const* d_in, const int* in_sizes, int n_in,
                              void* d_out, int out_size)
{
    const float* h        = (const float*)d_in[0];
    const float* e        = (const float*)d_in[1];
    const float* ln_h_g   = (const float*)d_in[2];
    const float* ln_h_b   = (const float*)d_in[3];
    const float* ln_e_g   = (const float*)d_in[4];
    const float* ln_e_b   = (const float*)d_in[5];
    const float* W_E      = (const float*)d_in[6];
    const float* b_E      = (const float*)d_in[7];
    const float* W_QKV    = (const float*)d_in[8];
    const float* b_QKV    = (const float*)d_in[9];
    const float* W_G      = (const float*)d_in[10];
    const float* b_G      = (const float*)d_in[11];
    const float* W_Oh     = (const float*)d_in[12];
    const float* b_Oh     = (const float*)d_in[13];
    const float* ffn_ln_h_g = (const float*)d_in[14];
    const float* ffn_ln_h_b = (const float*)d_in[15];
    const float* W_h1     = (const float*)d_in[16];
    const float* b_h1     = (const float*)d_in[17];
    const float* W_h2     = (const float*)d_in[18];
    const float* b_h2     = (const float*)d_in[19];
    const float* W_Oe     = (const float*)d_in[20];
    const float* b_Oe     = (const float*)d_in[21];
    const float* ffn_ln_e_g = (const float*)d_in[22];
    const float* ffn_ln_e_b = (const float*)d_in[23];
    const float* W_e1     = (const float*)d_in[24];
    const float* b_e1     = (const float*)d_in[25];
    const float* W_e2     = (const float*)d_in[26];
    const float* b_e2     = (const float*)d_in[27];

    float* out_h = (float*)d_out;
    float* out_e = out_h + H_OUT_ELEMS;

    float *p_hln, *p_qkv, *p_vatt, *p_h1, *p_h2, *p_act;
    cudaGetSymbolAddress((void**)&p_hln,  g_hln);
    cudaGetSymbolAddress((void**)&p_qkv,  g_qkv);
    cudaGetSymbolAddress((void**)&p_vatt, g_vatt);
    cudaGetSymbolAddress((void**)&p_h1,   g_h1);
    cudaGetSymbolAddress((void**)&p_h2,   g_h2);
    cudaGetSymbolAddress((void**)&p_act,  g_act);

    // h path pre-attention
    ln1024_kernel<<<BN, 256>>>(h, ln_h_g, ln_h_b, p_hln);
    gemm_tc_kernel<<<dim3(3*NDIM/128, BN/128), 256>>>(p_hln, W_QKV, b_QKV, nullptr, p_qkv,
                                                      BN, 3*NDIM, NDIM, 0);
    // e path: LN + E/G projections
    eg_kernel<<<(unsigned)(EROWS/64), 256>>>(e, ln_e_g, ln_e_b, W_E, b_E, W_G, b_G);
    // attention
    qk_kernel<<<dim3(8, 8, BHN), 256>>>(p_qkv);
    softmax_kernel<<<BHN*NSEQ, 256>>>();
    av_kernel<<<dim3(8, BHN), 256>>>(p_qkv);
    // h path post-attention
    gemm_tc_kernel<<<dim3(NDIM/128, BN/128), 256>>>(p_vatt, W_Oh, b_Oh, h, p_h1,
                                                    BN, NDIM, NDIM, 0);
    ln1024_kernel<<<BN, 256>>>(p_h1, ffn_ln_h_g, ffn_ln_h_b, p_h2);
    gemm_tc_kernel<<<dim3(FFN_H/128, BN/128), 256>>>(p_h2, W_h1, b_h1, nullptr, p_act,
                                                     BN, FFN_H, NDIM, 1);
    gemm_tc_kernel<<<dim3(NDIM/128, BN/128), 256>>>(p_act, W_h2, b_h2, p_h1, out_h,
                                                    BN, NDIM, FFN_H, 0);
    // fused e output path
    cudaFuncSetAttribute(eout_kernel, cudaFuncAttributeMaxDynamicSharedMemorySize,
                         EOUT_SMEM_FLOATS * 4);
    eout_kernel<<<(unsigned)(EROWS/128), 512, EOUT_SMEM_FLOATS * 4>>>(
        e, W_Oe, b_Oe, ffn_ln_e_g, ffn_ln_e_b, W_e1, b_e1, W_e2, b_e2, out_e);
}

// round 4
// speedup vs baseline: 1.8376x; 1.0703x over previous
#include <cuda_runtime.h>
#include <cuda_bf16.h>
#include <math.h>

// ---------------- problem constants ----------------
#define BATCH   4
#define NSEQ    512
#define NDIM    1024
#define EDIM    64
#define HEADS   16
#define DOTD    64
#define FFN_H   2048
#define FFN_E   128
#define BN      (BATCH*NSEQ)          // 2048 token rows
#define NN      (NSEQ*NSEQ)           // 262144 per batch
#define BHN     (BATCH*HEADS)         // 64
#define EROWS   ((size_t)BATCH*NSEQ*NSEQ) // 1048576 edge rows
#define H_OUT_ELEMS (BN*NDIM)         // 2097152

// ---------------- scratch (device globals; no allocs allowed) ----------------
__device__ float g_hln [BN*NDIM];
__device__ float g_qkv [BN*3*NDIM];
__device__ float g_E   [(size_t)BHN*NN];   // (b*16+h, l*512+m)
__device__ float g_gate[(size_t)BHN*NN];
__device__ float g_H   [(size_t)BHN*NN];   // H_hat = clip(A)+E
__device__ float g_At  [(size_t)BHN*NN];   // softmax*gates
__device__ float g_vatt[BN*NDIM];
__device__ float g_h1  [BN*NDIM];          // h after O_h + residual
__device__ float g_h2  [BN*NDIM];          // LN of g_h1
__device__ float g_act [BN*FFN_H];

// ---------------- LayerNorm over 1024 ----------------
__global__ void __launch_bounds__(256) ln1024_kernel(
    const float* __restrict__ x, const float* __restrict__ g,
    const float* __restrict__ b, float* __restrict__ y)
{
    int row = blockIdx.x, t = threadIdx.x;
    const float* xr = x + (size_t)row * NDIM;
    float v[4]; float s = 0.f;
#pragma unroll
    for (int i = 0; i < 4; i++) { v[i] = xr[t + i*256]; s += v[i]; }
    __shared__ float red[8];
    int lane = t & 31, w = t >> 5;
#pragma unroll
    for (int o = 16; o; o >>= 1) s += __shfl_xor_sync(0xffffffff, s, o);
    if (lane == 0) red[w] = s;
    __syncthreads();
    float tot = 0.f;
#pragma unroll
    for (int i = 0; i < 8; i++) tot += red[i];
    float mu = tot * (1.0f/NDIM);
    __syncthreads();
    float q = 0.f;
#pragma unroll
    for (int i = 0; i < 4; i++) { float d = v[i]-mu; q += d*d; }
#pragma unroll
    for (int o = 16; o; o >>= 1) q += __shfl_xor_sync(0xffffffff, q, o);
    if (lane == 0) red[w] = q;
    __syncthreads();
    float qt = 0.f;
#pragma unroll
    for (int i = 0; i < 8; i++) qt += red[i];
    float rs = rsqrtf(qt * (1.0f/NDIM) + 1e-5f);
    float* yr = y + (size_t)row * NDIM;
#pragma unroll
    for (int i = 0; i < 4; i++) {
        int c = t + i*256;
        yr[c] = (v[i]-mu)*rs*g[c] + b[c];
    }
}

// ---------------- tf32 helpers ----------------
__device__ __forceinline__ float f2tf(float x) {
    unsigned r;
    asm("cvt.rna.tf32.f32 %0, %1;" : "=r"(r) : "f"(x));
    return __uint_as_float(r);
}

__device__ __forceinline__ void mma_tf32(float* c, const unsigned* a, const unsigned* b) {
    asm volatile(
        "mma.sync.aligned.m16n8k8.row.col.f32.tf32.tf32.f32 "
        "{%0,%1,%2,%3}, {%4,%5,%6,%7}, {%8,%9}, {%0,%1,%2,%3};\n"
        : "+f"(c[0]), "+f"(c[1]), "+f"(c[2]), "+f"(c[3])
        : "r"(a[0]), "r"(a[1]), "r"(a[2]), "r"(a[3]), "r"(b[0]), "r"(b[1]));
}

// ---------------- tf32 tensor-core GEMM: C = act(A@W + bias) (+res) ----------------
// 128x128 tile, BK=16, 256 threads (8 warps), warp tile 32x64.
#define AS_LD 17
#define BS_LD 132
__global__ void __launch_bounds__(256) gemm_tc_kernel(
    const float* __restrict__ A, const float* __restrict__ W,
    const float* __restrict__ bias, const float* __restrict__ res,
    float* __restrict__ C, int M, int N, int K, int act)
{
    __shared__ float As[2][128*AS_LD];
    __shared__ float Bs[2][16*BS_LD];

    int t = threadIdx.x;
    int lane = t & 31;
    int w = t >> 5;
    int wm = w & 3;            // 4 m-tiles of 32 rows
    int wn = w >> 2;           // 2 n-tiles of 64 cols
    int qr = lane >> 2;        // 0..7
    int qc = lane & 3;         // 0..3
    int n0 = blockIdx.x * 128, m0 = blockIdx.y * 128;

    int arow = t >> 1;             // 0..127
    int acol = (t & 1) * 8;        // 0 or 8
    int brow = t >> 4;             // 0..15
    int bcol = (t & 15) * 8;       // 0..120

    const float* Aptr = A + (size_t)(m0 + arow)*K + acol;
    const float* Bptr = W + (size_t)brow*N + n0 + bcol;

    float acc[2][8][4];
#pragma unroll
    for (int i = 0; i < 2; i++)
#pragma unroll
        for (int j = 0; j < 8; j++)
#pragma unroll
            for (int k = 0; k < 4; k++) acc[i][j][k] = 0.f;

    int KT = K / 16;
    float4 ra0, ra1, rb0, rb1;
    ra0 = *(const float4*)(Aptr + 0);
    ra1 = *(const float4*)(Aptr + 4);
    rb0 = *(const float4*)(Bptr + 0);
    rb1 = *(const float4*)(Bptr + 4);
    {
        float* as = As[0]; float* bs = Bs[0];
        int sa = arow*AS_LD + acol;
        as[sa+0]=f2tf(ra0.x); as[sa+1]=f2tf(ra0.y); as[sa+2]=f2tf(ra0.z); as[sa+3]=f2tf(ra0.w);
        as[sa+4]=f2tf(ra1.x); as[sa+5]=f2tf(ra1.y); as[sa+6]=f2tf(ra1.z); as[sa+7]=f2tf(ra1.w);
        int sb = brow*BS_LD + bcol;
        bs[sb+0]=f2tf(rb0.x); bs[sb+1]=f2tf(rb0.y); bs[sb+2]=f2tf(rb0.z); bs[sb+3]=f2tf(rb0.w);
        bs[sb+4]=f2tf(rb1.x); bs[sb+5]=f2tf(rb1.y); bs[sb+6]=f2tf(rb1.z); bs[sb+7]=f2tf(rb1.w);
    }
    __syncthreads();

    for (int kt = 0; kt < KT; kt++) {
        int cur = kt & 1;
        if (kt + 1 < KT) {
            int k0 = (kt + 1) * 16;
            ra0 = *(const float4*)(Aptr + k0);
            ra1 = *(const float4*)(Aptr + k0 + 4);
            rb0 = *(const float4*)(Bptr + (size_t)k0*N);
            rb1 = *(const float4*)(Bptr + (size_t)k0*N + 4);
        }
        const float* as = As[cur];
        const float* bs = Bs[cur];
#pragma unroll
        for (int ks = 0; ks < 2; ks++) {
            int k = ks * 8;
            unsigned af[2][4];
#pragma unroll
            for (int mt = 0; mt < 2; mt++) {
                int r0 = (wm*32 + mt*16 + qr) * AS_LD + k + qc;
                af[mt][0] = __float_as_uint(as[r0]);
                af[mt][1] = __float_as_uint(as[r0 + 8*AS_LD]);
                af[mt][2] = __float_as_uint(as[r0 + 4]);
                af[mt][3] = __float_as_uint(as[r0 + 8*AS_LD + 4]);
            }
            unsigned bf[8][2];
#pragma unroll
            for (int nt = 0; nt < 8; nt++) {
                int c0 = (k + qc)*BS_LD + wn*64 + nt*8 + qr;
                bf[nt][0] = __float_as_uint(bs[c0]);
                bf[nt][1] = __float_as_uint(bs[c0 + 4*BS_LD]);
            }
#pragma unroll
            for (int mt = 0; mt < 2; mt++)
#pragma unroll
                for (int nt = 0; nt < 8; nt++)
                    mma_tf32(acc[mt][nt], af[mt], bf[nt]);
        }
        if (kt + 1 < KT) {
            float* asw = As[cur ^ 1]; float* bsw = Bs[cur ^ 1];
            int sa = arow*AS_LD + acol;
            asw[sa+0]=f2tf(ra0.x); asw[sa+1]=f2tf(ra0.y); asw[sa+2]=f2tf(ra0.z); asw[sa+3]=f2tf(ra0.w);
            asw[sa+4]=f2tf(ra1.x); asw[sa+5]=f2tf(ra1.y); asw[sa+6]=f2tf(ra1.z); asw[sa+7]=f2tf(ra1.w);
            int sb = brow*BS_LD + bcol;
            bsw[sb+0]=f2tf(rb0.x); bsw[sb+1]=f2tf(rb0.y); bsw[sb+2]=f2tf(rb0.z); bsw[sb+3]=f2tf(rb0.w);
            bsw[sb+4]=f2tf(rb1.x); bsw[sb+5]=f2tf(rb1.y); bsw[sb+6]=f2tf(rb1.z); bsw[sb+7]=f2tf(rb1.w);
        }
        __syncthreads();
    }

    // epilogue
#pragma unroll
    for (int mt = 0; mt < 2; mt++) {
        int mA = m0 + wm*32 + mt*16 + qr;
        int mB = mA + 8;
#pragma unroll
        for (int nt = 0; nt < 8; nt++) {
            int n = n0 + wn*64 + nt*8 + qc*2;
            float b0 = bias[n], b1 = bias[n + 1];
            float v0 = acc[mt][nt][0] + b0;
            float v1 = acc[mt][nt][1] + b1;
            float v2 = acc[mt][nt][2] + b0;
            float v3 = acc[mt][nt][3] + b1;
            if (act) {
                v0 = v0 > 0.f ? v0 : expm1f(v0);
                v1 = v1 > 0.f ? v1 : expm1f(v1);
                v2 = v2 > 0.f ? v2 : expm1f(v2);
                v3 = v3 > 0.f ? v3 : expm1f(v3);
            }
            if (res) {
                const float* rA = res + (size_t)mA*N + n;
                const float* rB = res + (size_t)mB*N + n;
                v0 += rA[0]; v1 += rA[1];
                v2 += rB[0]; v3 += rB[1];
            }
            float2 oA; oA.x = v0; oA.y = v1;
            float2 oB; oB.x = v2; oB.y = v3;
            *(float2*)(C + (size_t)mA*N + n) = oA;
            *(float2*)(C + (size_t)mB*N + n) = oB;
        }
    }
}

// ---------------- e -> LN -> E proj, sigmoid(G proj) ----------------
__global__ void __launch_bounds__(256) eg_kernel(
    const float* __restrict__ e,
    const float* __restrict__ lng, const float* __restrict__ lnb,
    const float* __restrict__ WE, const float* __restrict__ bE,
    const float* __restrict__ WG, const float* __restrict__ bG)
{
    __shared__ float xs[64*65];
    __shared__ float wE[64*16], wG[64*16];
    __shared__ float ob[32*65];
    __shared__ float sg[64], sb[64], sbE[16], sbG[16];
    int t = threadIdx.x;
    size_t row0 = (size_t)blockIdx.x * 64;

    for (int i = t; i < 1024; i += 256) { wE[i] = WE[i]; wG[i] = WG[i]; }
    if (t < 64) { sg[t] = lng[t]; sb[t] = lnb[t]; }
    if (t < 16) { sbE[t] = bE[t]; sbG[t] = bG[t]; }
#pragma unroll
    for (int i = 0; i < 16; i++) {
        int idx = t + i*256;
        int r = idx >> 6, c = idx & 63;
        xs[r*65 + c] = e[row0*64 + idx];
    }
    __syncthreads();
    {
        int r = t >> 2, part = t & 3;
        float lv[16]; float s = 0.f;
#pragma unroll
        for (int k = 0; k < 16; k++) { lv[k] = xs[r*65 + part*16 + k]; s += lv[k]; }
        s += __shfl_xor_sync(0xffffffff, s, 1);
        s += __shfl_xor_sync(0xffffffff, s, 2);
        float mu = s * (1.0f/64.0f);
        float q = 0.f;
#pragma unroll
        for (int k = 0; k < 16; k++) { float d = lv[k]-mu; q += d*d; }
        q += __shfl_xor_sync(0xffffffff, q, 1);
        q += __shfl_xor_sync(0xffffffff, q, 2);
        float rsg = rsqrtf(q * (1.0f/64.0f) + 1e-5f);
#pragma unroll
        for (int k = 0; k < 16; k++) {
            int c = part*16 + k;
            xs[r*65 + c] = (lv[k]-mu)*rsg*sg[c] + sb[c];
        }
    }
    __syncthreads();
    {
        int o = t & 31, rg = t >> 5;
        bool isE = (o < 16);
        int oo = isE ? o : o - 16;
        const float* wp = isE ? wE : wG;
#pragma unroll
        for (int i = 0; i < 8; i++) {
            int rr = rg*8 + i;
            float a = 0.f;
#pragma unroll
            for (int k = 0; k < 64; k++) a += xs[rr*65 + k] * wp[k*16 + oo];
            a += isE ? sbE[oo] : sbG[oo];
            if (!isE) a = 1.0f / (1.0f + expf(-a));
            ob[o*65 + rr] = a;
        }
    }
    __syncthreads();
    int b_ = (int)(row0 >> 18);
    int rem = (int)(row0 & (NN - 1));
    int l = rem >> 9, m0 = rem & 511;
#pragma unroll
    for (int i = 0; i < 8; i++) {
        int idx = t + i*256;
        int o = idx >> 6, rr = idx & 63;
        float val = ob[o*65 + rr];
        int hd = o & 15;
        size_t dst = ((size_t)(b_*HEADS + hd))*NN + (size_t)l*512 + m0 + rr;
        if (o < 16) g_E[dst] = val; else g_gate[dst] = val;
    }
}

// ---------------- Q@K^T, scale, clip, +E -> H_hat ----------------
__global__ void __launch_bounds__(256) qk_kernel(const float* __restrict__ qkv)
{
    __shared__ float Qs[64*65];  // [d][l]
    __shared__ float Ks[64*65];  // [d][m]
    int t = threadIdx.x;
    int m0 = blockIdx.x * 64, l0 = blockIdx.y * 64;
    int z = blockIdx.z;
    int b = z >> 4, hd = z & 15;
    const float* qb = qkv + (size_t)b*NSEQ*3*NDIM + hd;
#pragma unroll
    for (int i = 0; i < 16; i++) {
        int idx = t + i*256;
        int d = idx & 63, r = idx >> 6;
        Qs[d*65 + r] = qb[(size_t)(l0 + r)*(3*NDIM) + d*16];
        Ks[d*65 + r] = qb[(size_t)(m0 + r)*(3*NDIM) + NDIM + d*16];
    }
    __syncthreads();
    int tx = t & 15, ty = t >> 4;
    float acc[4][4];
#pragma unroll
    for (int i = 0; i < 4; i++)
#pragma unroll
        for (int j = 0; j < 4; j++) acc[i][j] = 0.f;
#pragma unroll 4
    for (int d = 0; d < 64; d++) {
        float a[4], bb[4];
#pragma unroll
        for (int i = 0; i < 4; i++) a[i]  = Qs[d*65 + ty*4 + i];
#pragma unroll
        for (int j = 0; j < 4; j++) bb[j] = Ks[d*65 + tx*4 + j];
#pragma unroll
        for (int i = 0; i < 4; i++)
#pragma unroll
            for (int j = 0; j < 4; j++) acc[i][j] += a[i]*bb[j];
    }
    size_t base = (size_t)z * NN;
#pragma unroll
    for (int i = 0; i < 4; i++) {
        int l = l0 + ty*4 + i;
        size_t ro = base + (size_t)l*512 + m0 + tx*4;
        float4 ev = *(const float4*)&g_E[ro];
        float4 hv;
        hv.x = fminf(fmaxf(acc[i][0]*0.125f, -5.f), 5.f) + ev.x;
        hv.y = fminf(fmaxf(acc[i][1]*0.125f, -5.f), 5.f) + ev.y;
        hv.z = fminf(fmaxf(acc[i][2]*0.125f, -5.f), 5.f) + ev.z;
        hv.w = fminf(fmaxf(acc[i][3]*0.125f, -5.f), 5.f) + ev.w;
        *(float4*)&g_H[ro] = hv;
    }
}

// ---------------- softmax over m, * gates ----------------
__global__ void __launch_bounds__(256) softmax_kernel()
{
    int row = blockIdx.x;               // z*512 + l
    int t = threadIdx.x;
    size_t base = (size_t)row * 512;
    float v0 = g_H[base + t], v1 = g_H[base + 256 + t];
    __shared__ float red[8];
    int lane = t & 31, w = t >> 5;
    float mx = fmaxf(v0, v1);
#pragma unroll
    for (int o = 16; o; o >>= 1) mx = fmaxf(mx, __shfl_xor_sync(0xffffffff, mx, o));
    if (lane == 0) red[w] = mx;
    __syncthreads();
    float m = red[0];
#pragma unroll
    for (int i = 1; i < 8; i++) m = fmaxf(m, red[i]);
    __syncthreads();
    float e0 = expf(v0 - m), e1 = expf(v1 - m);
    float s = e0 + e1;
#pragma unroll
    for (int o = 16; o; o >>= 1) s += __shfl_xor_sync(0xffffffff, s, o);
    if (lane == 0) red[w] = s;
    __syncthreads();
    float tot = 0.f;
#pragma unroll
    for (int i = 0; i < 8; i++) tot += red[i];
    float inv = 1.0f / tot;
    g_At[base + t]       = e0 * inv * g_gate[base + t];
    g_At[base + 256 + t] = e1 * inv * g_gate[base + 256 + t];
}

// ---------------- A_tild @ V -> V_att (written in (b,l,k*16+h) layout) ----------------
__global__ void __launch_bounds__(256) av_kernel(const float* __restrict__ qkv)
{
    __shared__ float As[64*65]; // [m][l]
    __shared__ float Vs[64*64]; // [m][k]
    int t = threadIdx.x;
    int l0 = blockIdx.x * 64;
    int z = blockIdx.y;
    int b = z >> 4, hd = z & 15;
    int tx = t & 15, ty = t >> 4;
    const float* vb = qkv + (size_t)b*NSEQ*3*NDIM + 2*NDIM + hd;
    size_t abase = (size_t)z*NN + (size_t)l0*512;
    float acc[4][4];
#pragma unroll
    for (int i = 0; i < 4; i++)
#pragma unroll
        for (int j = 0; j < 4; j++) acc[i][j] = 0.f;

    for (int mt = 0; mt < 512; mt += 64) {
#pragma unroll
        for (int i = 0; i < 16; i++) {
            int idx = t + i*256;
            int c = idx & 63, r = idx >> 6;
            As[c*65 + r] = g_At[abase + (size_t)r*512 + mt + c];
            Vs[r*64 + c] = vb[(size_t)(mt + r)*(3*NDIM) + c*16];
        }
        __syncthreads();
#pragma unroll 4
        for (int m = 0; m < 64; m++) {
            float a[4], vv[4];
#pragma unroll
            for (int i = 0; i < 4; i++) a[i]  = As[m*65 + ty*4 + i];
#pragma unroll
            for (int j = 0; j < 4; j++) vv[j] = Vs[m*64 + tx*4 + j];
#pragma unroll
            for (int i = 0; i < 4; i++)
#pragma unroll
                for (int j = 0; j < 4; j++) acc[i][j] += a[i]*vv[j];
        }
        __syncthreads();
    }
#pragma unroll
    for (int i = 0; i < 4; i++) {
        int l = l0 + ty*4 + i;
#pragma unroll
        for (int j = 0; j < 4; j++) {
            int k = tx*4 + j;
            g_vatt[(size_t)(b*NSEQ + l)*NDIM + k*16 + hd] = acc[i][j];
        }
    }
}

// ---------------- fused e-out with tf32 mma FFN ----------------
// 64 edge rows per block, 256 threads (8 warps).
// smem layout (floats):
//  W1s  [64][132]  tf32   8448
//  W2s  [128][68]  tf32   8704
//  WOes [16][64]          1024
//  Hsm  [16][64]          1024
//  xs   [64][65]          4160   (x = H@WOe + bOe + e; residual)
//  xsn  [64][68]   tf32   4352   (LayerNorm(x))
//  hs   [64][132]  tf32   8448   (elu FFN hidden)
//  params                 512
#define EOUT_W1   0
#define EOUT_W2   8448
#define EOUT_WOE  17152
#define EOUT_HSM  18176
#define EOUT_XS   19200
#define EOUT_XSN  23360
#define EOUT_HS   27712
#define EOUT_PAR  36160
#define EOUT_SMEM_FLOATS 36672
__global__ void __launch_bounds__(256) eout_kernel(
    const float* __restrict__ e,
    const float* __restrict__ WOe, const float* __restrict__ bOe,
    const float* __restrict__ lng, const float* __restrict__ lnb,
    const float* __restrict__ W1, const float* __restrict__ b1,
    const float* __restrict__ W2, const float* __restrict__ b2,
    float* __restrict__ eout)
{
    extern __shared__ float sm[];
    float* W1s  = sm + EOUT_W1;    // [k=64][n=128] ld 132
    float* W2s  = sm + EOUT_W2;    // [k=128][n=64] ld 68
    float* WOes = sm + EOUT_WOE;
    float* Hsm  = sm + EOUT_HSM;
    float* xs   = sm + EOUT_XS;    // ld 65
    float* xsn  = sm + EOUT_XSN;   // ld 68
    float* hs   = sm + EOUT_HS;    // ld 132
    float* sbOe = sm + EOUT_PAR;        // 64
    float* sge  = sbOe + 64;            // 64
    float* sbe  = sge  + 64;            // 64
    float* sb1  = sbe  + 64;            // 128
    float* sb2  = sb1  + 128;           // 64
    float* smu  = sb2  + 64;            // 64
    float* srs  = smu  + 64;            // 64

    int t = threadIdx.x;
    size_t row0 = (size_t)blockIdx.x * 64;
    int b_ = (int)(row0 >> 18);
    int rem = (int)(row0 & (NN - 1));
    int l = rem >> 9, m0 = rem & 511;

    // stage weights (tf32) + params
    for (int i = t; i < 8192; i += 256) {
        W1s[(i >> 7)*132 + (i & 127)] = f2tf(W1[i]);
        W2s[(i >> 6)*68  + (i & 63)]  = f2tf(W2[i]);
    }
    for (int i = t; i < 1024; i += 256) {
        WOes[i] = WOe[i];
        int hd = i >> 6, r = i & 63;
        Hsm[hd*64 + r] = g_H[((size_t)(b_*HEADS + hd))*NN + (size_t)l*512 + m0 + r];
    }
    if (t < 64) { sbOe[t] = bOe[t]; sge[t] = lng[t]; sbe[t] = lnb[t]; sb2[t] = b2[t]; }
    if (t >= 64 && t < 192) sb1[t - 64] = b1[t - 64];
    __syncthreads();

    int lane = t & 31;
    int w = t >> 5;
    int wm = w & 3;           // 16-row tiles
    int wn = w >> 2;          // phase C: 64-col tiles, phase E: 32-col tiles
    int qr = lane >> 2, qc = lane & 3;
    int tx = t & 15, ty = t >> 4;

    // Phase A: xs = H@WOe + bOe + e  (64 x 64), scalar (tiny K=16)
    {
        float acc[4][4];
#pragma unroll
        for (int i = 0; i < 4; i++)
#pragma unroll
            for (int j = 0; j < 4; j++) acc[i][j] = 0.f;
#pragma unroll
        for (int hd = 0; hd < 16; hd++) {
            float a[4], wv[4];
#pragma unroll
            for (int i = 0; i < 4; i++) a[i] = Hsm[hd*64 + ty*4 + i];
#pragma unroll
            for (int j = 0; j < 4; j++) wv[j] = WOes[hd*64 + tx*4 + j];
#pragma unroll
            for (int i = 0; i < 4; i++)
#pragma unroll
                for (int j = 0; j < 4; j++) acc[i][j] += a[i]*wv[j];
        }
#pragma unroll
        for (int i = 0; i < 4; i++) {
            int r = ty*4 + i;
            float4 ev = *(const float4*)&e[(row0 + r)*64 + tx*4];
            xs[r*65 + tx*4 + 0] = acc[i][0] + sbOe[tx*4+0] + ev.x;
            xs[r*65 + tx*4 + 1] = acc[i][1] + sbOe[tx*4+1] + ev.y;
            xs[r*65 + tx*4 + 2] = acc[i][2] + sbOe[tx*4+2] + ev.z;
            xs[r*65 + tx*4 + 3] = acc[i][3] + sbOe[tx*4+3] + ev.w;
        }
    }
    __syncthreads();

    // Phase B: LN stats (256 threads, 4 per row)
    {
        int r = t >> 2, part = t & 3;
        float lv[16]; float s = 0.f;
#pragma unroll
        for (int k = 0; k < 16; k++) { lv[k] = xs[r*65 + part*16 + k]; s += lv[k]; }
        s += __shfl_xor_sync(0xffffffff, s, 1);
        s += __shfl_xor_sync(0xffffffff, s, 2);
        float mu = s * (1.0f/64.0f);
        float q = 0.f;
#pragma unroll
        for (int k = 0; k < 16; k++) { float d = lv[k]-mu; q += d*d; }
        q += __shfl_xor_sync(0xffffffff, q, 1);
        q += __shfl_xor_sync(0xffffffff, q, 2);
        if (part == 0) { smu[r] = mu; srs[r] = rsqrtf(q*(1.0f/64.0f) + 1e-5f); }
    }
    __syncthreads();

    // Phase B2: xsn = tf32(LN(xs))
#pragma unroll
    for (int i = 0; i < 16; i++) {
        int idx = t + i*256;
        int r = idx >> 6, k = idx & 63;
        xsn[r*68 + k] = f2tf((xs[r*65 + k] - smu[r]) * srs[r] * sge[k] + sbe[k]);
    }
    __syncthreads();

    // Phase C (mma): hidden = elu( xsn @ W1 + b1 )  [64 x 128], K=64
    {
        float acc[8][4];
#pragma unroll
        for (int j = 0; j < 8; j++)
#pragma unroll
            for (int k = 0; k < 4; k++) acc[j][k] = 0.f;
#pragma unroll
        for (int k8 = 0; k8 < 8; k8++) {
            int k = k8 * 8;
            unsigned af[4];
            int r0 = (wm*16 + qr)*68 + k + qc;
            af[0] = __float_as_uint(xsn[r0]);
            af[1] = __float_as_uint(xsn[r0 + 8*68]);
            af[2] = __float_as_uint(xsn[r0 + 4]);
            af[3] = __float_as_uint(xsn[r0 + 8*68 + 4]);
#pragma unroll
            for (int nt = 0; nt < 8; nt++) {
                int c0 = (k + qc)*132 + wn*64 + nt*8 + qr;
                unsigned bf[2];
                bf[0] = __float_as_uint(W1s[c0]);
                bf[1] = __float_as_uint(W1s[c0 + 4*132]);
                mma_tf32(acc[nt], af, bf);
            }
        }
#pragma unroll
        for (int nt = 0; nt < 8; nt++) {
            int n = wn*64 + nt*8 + qc*2;
            int mA = wm*16 + qr, mB = mA + 8;
            float v0 = acc[nt][0] + sb1[n];
            float v1 = acc[nt][1] + sb1[n+1];
            float v2 = acc[nt][2] + sb1[n];
            float v3 = acc[nt][3] + sb1[n+1];
            v0 = v0 > 0.f ? v0 : expm1f(v0);
            v1 = v1 > 0.f ? v1 : expm1f(v1);
            v2 = v2 > 0.f ? v2 : expm1f(v2);
            v3 = v3 > 0.f ? v3 : expm1f(v3);
            hs[mA*132 + n]     = f2tf(v0);
            hs[mA*132 + n + 1] = f2tf(v1);
            hs[mB*132 + n]     = f2tf(v2);
            hs[mB*132 + n + 1] = f2tf(v3);
        }
    }
    __syncthreads();

    // Phase E (mma): out = hs @ W2 + b2 + xs  [64 x 64], K=128
    {
        float acc[4][4];
#pragma unroll
        for (int j = 0; j < 4; j++)
#pragma unroll
            for (int k = 0; k < 4; k++) acc[j][k] = 0.f;
#pragma unroll
        for (int k8 = 0; k8 < 16; k8++) {
            int k = k8 * 8;
            unsigned af[4];
            int r0 = (wm*16 + qr)*132 + k + qc;
            af[0] = __float_as_uint(hs[r0]);
            af[1] = __float_as_uint(hs[r0 + 8*132]);
            af[2] = __float_as_uint(hs[r0 + 4]);
            af[3] = __float_as_uint(hs[r0 + 8*132 + 4]);
#pragma unroll
            for (int nt = 0; nt < 4; nt++) {
                int c0 = (k + qc)*68 + wn*32 + nt*8 + qr;
                unsigned bf[2];
                bf[0] = __float_as_uint(W2s[c0]);
                bf[1] = __float_as_uint(W2s[c0 + 4*68]);
                mma_tf32(acc[nt], af, bf);
            }
        }
#pragma unroll
        for (int nt = 0; nt < 4; nt++) {
            int n = wn*32 + nt*8 + qc*2;
            int mA = wm*16 + qr, mB = mA + 8;
            float2 oA, oB;
            oA.x = acc[nt][0] + sb2[n]   + xs[mA*65 + n];
            oA.y = acc[nt][1] + sb2[n+1] + xs[mA*65 + n + 1];
            oB.x = acc[nt][2] + sb2[n]   + xs[mB*65 + n];
            oB.y = acc[nt][3] + sb2[n+1] + xs[mB*65 + n + 1];
            *(float2*)&eout[(row0 + mA)*64 + n] = oA;
            *(float2*)&eout[(row0 + mB)*64 + n] = oB;
        }
    }
}

// ---------------- host launcher ----------------
extern "C" void kernel_launch(void* const* d_in, const int* in_sizes, int n_in,
                              void* d_out, int out_size)
{
    const float* h        = (const float*)d_in[0];
    const float* e        = (const float*)d_in[1];
    const float* ln_h_g   = (const float*)d_in[2];
    const float* ln_h_b   = (const float*)d_in[3];
    const float* ln_e_g   = (const float*)d_in[4];
    const float* ln_e_b   = (const float*)d_in[5];
    const float* W_E      = (const float*)d_in[6];
    const float* b_E      = (const float*)d_in[7];
    const float* W_QKV    = (const float*)d_in[8];
    const float* b_QKV    = (const float*)d_in[9];
    const float* W_G      = (const float*)d_in[10];
    const float* b_G      = (const float*)d_in[11];
    const float* W_Oh     = (const float*)d_in[12];
    const float* b_Oh     = (const float*)d_in[13];
    const float* ffn_ln_h_g = (const float*)d_in[14];
    const float* ffn_ln_h_b = (const float*)d_in[15];
    const float* W_h1     = (const float*)d_in[16];
    const float* b_h1     = (const float*)d_in[17];
    const float* W_h2     = (const float*)d_in[18];
    const float* b_h2     = (const float*)d_in[19];
    const float* W_Oe     = (const float*)d_in[20];
    const float* b_Oe     = (const float*)d_in[21];
    const float* ffn_ln_e_g = (const float*)d_in[22];
    const float* ffn_ln_e_b = (const float*)d_in[23];
    const float* W_e1     = (const float*)d_in[24];
    const float* b_e1     = (const float*)d_in[25];
    const float* W_e2     = (const float*)d_in[26];
    const float* b_e2     = (const float*)d_in[27];

    float* out_h = (float*)d_out;
    float* out_e = out_h + H_OUT_ELEMS;

    float *p_hln, *p_qkv, *p_vatt, *p_h1, *p_h2, *p_act;
    cudaGetSymbolAddress((void**)&p_hln,  g_hln);
    cudaGetSymbolAddress((void**)&p_qkv,  g_qkv);
    cudaGetSymbolAddress((void**)&p_vatt, g_vatt);
    cudaGetSymbolAddress((void**)&p_h1,   g_h1);
    cudaGetSymbolAddress((void**)&p_h2,   g_h2);
    cudaGetSymbolAddress((void**)&p_act,  g_act);

    // h path pre-attention
    ln1024_kernel<<<BN, 256>>>(h, ln_h_g, ln_h_b, p_hln);
    gemm_tc_kernel<<<dim3(3*NDIM/128, BN/128), 256>>>(p_hln, W_QKV, b_QKV, nullptr, p_qkv,
                                                      BN, 3*NDIM, NDIM, 0);
    // e path: LN + E/G projections
    eg_kernel<<<(unsigned)(EROWS/64), 256>>>(e, ln_e_g, ln_e_b, W_E, b_E, W_G, b_G);
    // attention
    qk_kernel<<<dim3(8, 8, BHN), 256>>>(p_qkv);
    softmax_kernel<<<BHN*NSEQ, 256>>>();
    av_kernel<<<dim3(8, BHN), 256>>>(p_qkv);
    // h path post-attention
    gemm_tc_kernel<<<dim3(NDIM/128, BN/128), 256>>>(p_vatt, W_Oh, b_Oh, h, p_h1,
                                                    BN, NDIM, NDIM, 0);
    ln1024_kernel<<<BN, 256>>>(p_h1, ffn_ln_h_g, ffn_ln_h_b, p_h2);
    gemm_tc_kernel<<<dim3(FFN_H/128, BN/128), 256>>>(p_h2, W_h1, b_h1, nullptr, p_act,
                                                     BN, FFN_H, NDIM, 1);
    gemm_tc_kernel<<<dim3(NDIM/128, BN/128), 256>>>(p_act, W_h2, b_h2, p_h1, out_h,
                                                    BN, NDIM, FFN_H, 0);
    // fused e output path (tf32 mma FFN)
    cudaFuncSetAttribute(eout_kernel, cudaFuncAttributeMaxDynamicSharedMemorySize,
                         EOUT_SMEM_FLOATS * 4);
    eout_kernel<<<(unsigned)(EROWS/64), 256, EOUT_SMEM_FLOATS * 4>>>(
        e, W_Oe, b_Oe, ffn_ln_e_g, ffn_ln_e_b, W_e1, b_e1, W_e2, b_e2, out_e);
}

// round 5
// speedup vs baseline: 2.0828x; 1.1335x over previous
#include <cuda_runtime.h>
#include <cuda_bf16.h>
#include <math.h>

// ---------------- problem constants ----------------
#define BATCH   4
#define NSEQ    512
#define NDIM    1024
#define EDIM    64
#define HEADS   16
#define DOTD    64
#define FFN_H   2048
#define FFN_E   128
#define BN      (BATCH*NSEQ)          // 2048 token rows
#define NN      (NSEQ*NSEQ)           // 262144 per batch
#define BHN     (BATCH*HEADS)         // 64
#define EROWS   ((size_t)BATCH*NSEQ*NSEQ) // 1048576 edge rows
#define H_OUT_ELEMS (BN*NDIM)         // 2097152

// ---------------- scratch (device globals; no allocs allowed) ----------------
__device__ float g_hln [BN*NDIM];
__device__ float g_qkv [BN*3*NDIM];
__device__ float g_E   [(size_t)BHN*NN];   // (b*16+h, l*512+m)
__device__ float g_gate[(size_t)BHN*NN];
__device__ float g_H   [(size_t)BHN*NN];   // H_hat = clip(A)+E
__device__ float g_vatt[BN*NDIM];
__device__ float g_h1  [BN*NDIM];          // h after O_h + residual
__device__ float g_h2  [BN*NDIM];          // LN of g_h1
__device__ float g_act [BN*FFN_H];

// ---------------- LayerNorm over 1024 ----------------
__global__ void __launch_bounds__(256) ln1024_kernel(
    const float* __restrict__ x, const float* __restrict__ g,
    const float* __restrict__ b, float* __restrict__ y)
{
    int row = blockIdx.x, t = threadIdx.x;
    const float* xr = x + (size_t)row * NDIM;
    float v[4]; float s = 0.f;
#pragma unroll
    for (int i = 0; i < 4; i++) { v[i] = xr[t + i*256]; s += v[i]; }
    __shared__ float red[8];
    int lane = t & 31, w = t >> 5;
#pragma unroll
    for (int o = 16; o; o >>= 1) s += __shfl_xor_sync(0xffffffff, s, o);
    if (lane == 0) red[w] = s;
    __syncthreads();
    float tot = 0.f;
#pragma unroll
    for (int i = 0; i < 8; i++) tot += red[i];
    float mu = tot * (1.0f/NDIM);
    __syncthreads();
    float q = 0.f;
#pragma unroll
    for (int i = 0; i < 4; i++) { float d = v[i]-mu; q += d*d; }
#pragma unroll
    for (int o = 16; o; o >>= 1) q += __shfl_xor_sync(0xffffffff, q, o);
    if (lane == 0) red[w] = q;
    __syncthreads();
    float qt = 0.f;
#pragma unroll
    for (int i = 0; i < 8; i++) qt += red[i];
    float rs = rsqrtf(qt * (1.0f/NDIM) + 1e-5f);
    float* yr = y + (size_t)row * NDIM;
#pragma unroll
    for (int i = 0; i < 4; i++) {
        int c = t + i*256;
        yr[c] = (v[i]-mu)*rs*g[c] + b[c];
    }
}

// ---------------- tf32 helpers ----------------
__device__ __forceinline__ float f2tf(float x) {
    unsigned r;
    asm("cvt.rna.tf32.f32 %0, %1;" : "=r"(r) : "f"(x));
    return __uint_as_float(r);
}

__device__ __forceinline__ void mma_tf32(float* c, const unsigned* a, const unsigned* b) {
    asm volatile(
        "mma.sync.aligned.m16n8k8.row.col.f32.tf32.tf32.f32 "
        "{%0,%1,%2,%3}, {%4,%5,%6,%7}, {%8,%9}, {%0,%1,%2,%3};\n"
        : "+f"(c[0]), "+f"(c[1]), "+f"(c[2]), "+f"(c[3])
        : "r"(a[0]), "r"(a[1]), "r"(a[2]), "r"(a[3]), "r"(b[0]), "r"(b[1]));
}

// ---------------- tf32 tensor-core GEMM: C = act(A@W + bias) (+res) ----------------
#define AS_LD 17
#define BS_LD 132
__global__ void __launch_bounds__(256) gemm_tc_kernel(
    const float* __restrict__ A, const float* __restrict__ W,
    const float* __restrict__ bias, const float* __restrict__ res,
    float* __restrict__ C, int M, int N, int K, int act)
{
    __shared__ float As[2][128*AS_LD];
    __shared__ float Bs[2][16*BS_LD];

    int t = threadIdx.x;
    int lane = t & 31;
    int w = t >> 5;
    int wm = w & 3;
    int wn = w >> 2;
    int qr = lane >> 2;
    int qc = lane & 3;
    int n0 = blockIdx.x * 128, m0 = blockIdx.y * 128;

    int arow = t >> 1;
    int acol = (t & 1) * 8;
    int brow = t >> 4;
    int bcol = (t & 15) * 8;

    const float* Aptr = A + (size_t)(m0 + arow)*K + acol;
    const float* Bptr = W + (size_t)brow*N + n0 + bcol;

    float acc[2][8][4];
#pragma unroll
    for (int i = 0; i < 2; i++)
#pragma unroll
        for (int j = 0; j < 8; j++)
#pragma unroll
            for (int k = 0; k < 4; k++) acc[i][j][k] = 0.f;

    int KT = K / 16;
    float4 ra0, ra1, rb0, rb1;
    ra0 = *(const float4*)(Aptr + 0);
    ra1 = *(const float4*)(Aptr + 4);
    rb0 = *(const float4*)(Bptr + 0);
    rb1 = *(const float4*)(Bptr + 4);
    {
        float* as = As[0]; float* bs = Bs[0];
        int sa = arow*AS_LD + acol;
        as[sa+0]=f2tf(ra0.x); as[sa+1]=f2tf(ra0.y); as[sa+2]=f2tf(ra0.z); as[sa+3]=f2tf(ra0.w);
        as[sa+4]=f2tf(ra1.x); as[sa+5]=f2tf(ra1.y); as[sa+6]=f2tf(ra1.z); as[sa+7]=f2tf(ra1.w);
        int sb = brow*BS_LD + bcol;
        bs[sb+0]=f2tf(rb0.x); bs[sb+1]=f2tf(rb0.y); bs[sb+2]=f2tf(rb0.z); bs[sb+3]=f2tf(rb0.w);
        bs[sb+4]=f2tf(rb1.x); bs[sb+5]=f2tf(rb1.y); bs[sb+6]=f2tf(rb1.z); bs[sb+7]=f2tf(rb1.w);
    }
    __syncthreads();

    for (int kt = 0; kt < KT; kt++) {
        int cur = kt & 1;
        if (kt + 1 < KT) {
            int k0 = (kt + 1) * 16;
            ra0 = *(const float4*)(Aptr + k0);
            ra1 = *(const float4*)(Aptr + k0 + 4);
            rb0 = *(const float4*)(Bptr + (size_t)k0*N);
            rb1 = *(const float4*)(Bptr + (size_t)k0*N + 4);
        }
        const float* as = As[cur];
        const float* bs = Bs[cur];
#pragma unroll
        for (int ks = 0; ks < 2; ks++) {
            int k = ks * 8;
            unsigned af[2][4];
#pragma unroll
            for (int mt = 0; mt < 2; mt++) {
                int r0 = (wm*32 + mt*16 + qr) * AS_LD + k + qc;
                af[mt][0] = __float_as_uint(as[r0]);
                af[mt][1] = __float_as_uint(as[r0 + 8*AS_LD]);
                af[mt][2] = __float_as_uint(as[r0 + 4]);
                af[mt][3] = __float_as_uint(as[r0 + 8*AS_LD + 4]);
            }
            unsigned bf[8][2];
#pragma unroll
            for (int nt = 0; nt < 8; nt++) {
                int c0 = (k + qc)*BS_LD + wn*64 + nt*8 + qr;
                bf[nt][0] = __float_as_uint(bs[c0]);
                bf[nt][1] = __float_as_uint(bs[c0 + 4*BS_LD]);
            }
#pragma unroll
            for (int mt = 0; mt < 2; mt++)
#pragma unroll
                for (int nt = 0; nt < 8; nt++)
                    mma_tf32(acc[mt][nt], af[mt], bf[nt]);
        }
        if (kt + 1 < KT) {
            float* asw = As[cur ^ 1]; float* bsw = Bs[cur ^ 1];
            int sa = arow*AS_LD + acol;
            asw[sa+0]=f2tf(ra0.x); asw[sa+1]=f2tf(ra0.y); asw[sa+2]=f2tf(ra0.z); asw[sa+3]=f2tf(ra0.w);
            asw[sa+4]=f2tf(ra1.x); asw[sa+5]=f2tf(ra1.y); asw[sa+6]=f2tf(ra1.z); asw[sa+7]=f2tf(ra1.w);
            int sb = brow*BS_LD + bcol;
            bsw[sb+0]=f2tf(rb0.x); bsw[sb+1]=f2tf(rb0.y); bsw[sb+2]=f2tf(rb0.z); bsw[sb+3]=f2tf(rb0.w);
            bsw[sb+4]=f2tf(rb1.x); bsw[sb+5]=f2tf(rb1.y); bsw[sb+6]=f2tf(rb1.z); bsw[sb+7]=f2tf(rb1.w);
        }
        __syncthreads();
    }

#pragma unroll
    for (int mt = 0; mt < 2; mt++) {
        int mA = m0 + wm*32 + mt*16 + qr;
        int mB = mA + 8;
#pragma unroll
        for (int nt = 0; nt < 8; nt++) {
            int n = n0 + wn*64 + nt*8 + qc*2;
            float b0 = bias[n], b1 = bias[n + 1];
            float v0 = acc[mt][nt][0] + b0;
            float v1 = acc[mt][nt][1] + b1;
            float v2 = acc[mt][nt][2] + b0;
            float v3 = acc[mt][nt][3] + b1;
            if (act) {
                v0 = v0 > 0.f ? v0 : expm1f(v0);
                v1 = v1 > 0.f ? v1 : expm1f(v1);
                v2 = v2 > 0.f ? v2 : expm1f(v2);
                v3 = v3 > 0.f ? v3 : expm1f(v3);
            }
            if (res) {
                const float* rA = res + (size_t)mA*N + n;
                const float* rB = res + (size_t)mB*N + n;
                v0 += rA[0]; v1 += rA[1];
                v2 += rB[0]; v3 += rB[1];
            }
            float2 oA; oA.x = v0; oA.y = v1;
            float2 oB; oB.x = v2; oB.y = v3;
            *(float2*)(C + (size_t)mA*N + n) = oA;
            *(float2*)(C + (size_t)mB*N + n) = oB;
        }
    }
}

// ---------------- e -> LN -> E proj, sigmoid(G proj) ----------------
__global__ void __launch_bounds__(256) eg_kernel(
    const float* __restrict__ e,
    const float* __restrict__ lng, const float* __restrict__ lnb,
    const float* __restrict__ WE, const float* __restrict__ bE,
    const float* __restrict__ WG, const float* __restrict__ bG)
{
    __shared__ float xs[64*65];
    __shared__ float wE[64*16], wG[64*16];
    __shared__ float ob[32*65];
    __shared__ float sg[64], sb[64], sbE[16], sbG[16];
    int t = threadIdx.x;
    size_t row0 = (size_t)blockIdx.x * 64;

    for (int i = t; i < 1024; i += 256) { wE[i] = WE[i]; wG[i] = WG[i]; }
    if (t < 64) { sg[t] = lng[t]; sb[t] = lnb[t]; }
    if (t < 16) { sbE[t] = bE[t]; sbG[t] = bG[t]; }
#pragma unroll
    for (int i = 0; i < 16; i++) {
        int idx = t + i*256;
        int r = idx >> 6, c = idx & 63;
        xs[r*65 + c] = e[row0*64 + idx];
    }
    __syncthreads();
    {
        int r = t >> 2, part = t & 3;
        float lv[16]; float s = 0.f;
#pragma unroll
        for (int k = 0; k < 16; k++) { lv[k] = xs[r*65 + part*16 + k]; s += lv[k]; }
        s += __shfl_xor_sync(0xffffffff, s, 1);
        s += __shfl_xor_sync(0xffffffff, s, 2);
        float mu = s * (1.0f/64.0f);
        float q = 0.f;
#pragma unroll
        for (int k = 0; k < 16; k++) { float d = lv[k]-mu; q += d*d; }
        q += __shfl_xor_sync(0xffffffff, q, 1);
        q += __shfl_xor_sync(0xffffffff, q, 2);
        float rsg = rsqrtf(q * (1.0f/64.0f) + 1e-5f);
#pragma unroll
        for (int k = 0; k < 16; k++) {
            int c = part*16 + k;
            xs[r*65 + c] = (lv[k]-mu)*rsg*sg[c] + sb[c];
        }
    }
    __syncthreads();
    {
        int o = t & 31, rg = t >> 5;
        bool isE = (o < 16);
        int oo = isE ? o : o - 16;
        const float* wp = isE ? wE : wG;
#pragma unroll
        for (int i = 0; i < 8; i++) {
            int rr = rg*8 + i;
            float a = 0.f;
#pragma unroll
            for (int k = 0; k < 64; k++) a += xs[rr*65 + k] * wp[k*16 + oo];
            a += isE ? sbE[oo] : sbG[oo];
            if (!isE) a = 1.0f / (1.0f + expf(-a));
            ob[o*65 + rr] = a;
        }
    }
    __syncthreads();
    int b_ = (int)(row0 >> 18);
    int rem = (int)(row0 & (NN - 1));
    int l = rem >> 9, m0 = rem & 511;
#pragma unroll
    for (int i = 0; i < 8; i++) {
        int idx = t + i*256;
        int o = idx >> 6, rr = idx & 63;
        float val = ob[o*65 + rr];
        int hd = o & 15;
        size_t dst = ((size_t)(b_*HEADS + hd))*NN + (size_t)l*512 + m0 + rr;
        if (o < 16) g_E[dst] = val; else g_gate[dst] = val;
    }
}

// ---------------- fused attention: QK^T+clip+E -> H (to gmem + smem),
//                  softmax*gate in smem, A@V -> vatt ----------------
// Block: 64 l-rows x 1 head. Grid (8, 64). 256 threads.
#define AV2_QS   0              // Qs[64][65]  [d][l]
#define AV2_KS   4160           // Ks[64][65]  [d][m]
#define AV2_VS   8320           // Vs[64][65]  [m][k]
#define AV2_HS   12480          // Hs[512][65] [m][l]
#define AV2_MX   45760          // 64
#define AV2_INV  45824          // 64
#define AV2_SMEM 45888
__global__ void __launch_bounds__(256) av2_kernel(const float* __restrict__ qkv)
{
    extern __shared__ float sm[];
    float* Qs  = sm + AV2_QS;
    float* Ks  = sm + AV2_KS;
    float* Vs  = sm + AV2_VS;
    float* Hs  = sm + AV2_HS;
    float* mxs = sm + AV2_MX;
    float* invs= sm + AV2_INV;

    int t = threadIdx.x;
    int l0 = blockIdx.x * 64;
    int z = blockIdx.y;
    int b = z >> 4, hd = z & 15;
    int tx = t & 15, ty = t >> 4;
    size_t zbase = (size_t)z * NN;
    const float* qb = qkv + (size_t)b*NSEQ*3*NDIM + hd;

    // load Q strip [d][l]
#pragma unroll
    for (int i = 0; i < 16; i++) {
        int idx = t + i*256;
        int d = idx & 63, r = idx >> 6;
        Qs[d*65 + r] = qb[(size_t)(l0 + r)*(3*NDIM) + d*16];
    }

    // Phase 1: per m-tile QK^T, clip, +E; write g_H and Hs
    for (int mt = 0; mt < 8; mt++) {
        int m0g = mt * 64;
#pragma unroll
        for (int i = 0; i < 16; i++) {
            int idx = t + i*256;
            int d = idx & 63, r = idx >> 6;
            Ks[d*65 + r] = qb[(size_t)(m0g + r)*(3*NDIM) + NDIM + d*16];
        }
        __syncthreads();
        float acc[4][4];
#pragma unroll
        for (int i = 0; i < 4; i++)
#pragma unroll
            for (int j = 0; j < 4; j++) acc[i][j] = 0.f;
#pragma unroll 4
        for (int d = 0; d < 64; d++) {
            float a[4], bb[4];
#pragma unroll
            for (int i = 0; i < 4; i++) a[i]  = Qs[d*65 + ty*4 + i];
#pragma unroll
            for (int j = 0; j < 4; j++) bb[j] = Ks[d*65 + tx*4 + j];
#pragma unroll
            for (int i = 0; i < 4; i++)
#pragma unroll
                for (int j = 0; j < 4; j++) acc[i][j] += a[i]*bb[j];
        }
#pragma unroll
        for (int i = 0; i < 4; i++) {
            int l = ty*4 + i;
            size_t ro = zbase + (size_t)(l0 + l)*512 + m0g + tx*4;
            float4 ev = *(const float4*)&g_E[ro];
            float4 hv;
            hv.x = fminf(fmaxf(acc[i][0]*0.125f, -5.f), 5.f) + ev.x;
            hv.y = fminf(fmaxf(acc[i][1]*0.125f, -5.f), 5.f) + ev.y;
            hv.z = fminf(fmaxf(acc[i][2]*0.125f, -5.f), 5.f) + ev.z;
            hv.w = fminf(fmaxf(acc[i][3]*0.125f, -5.f), 5.f) + ev.w;
            *(float4*)&g_H[ro] = hv;
            int mbase = m0g + tx*4;
            Hs[(mbase+0)*65 + l] = hv.x;
            Hs[(mbase+1)*65 + l] = hv.y;
            Hs[(mbase+2)*65 + l] = hv.z;
            Hs[(mbase+3)*65 + l] = hv.w;
        }
        __syncthreads();
    }

    // Phase 2: softmax stats per l-row (4 threads/row), exp stored back
    {
        int r = t >> 2, part = t & 3;
        float mx = -1e30f;
        for (int i = 0; i < 128; i++) {
            int m = part*128 + i;
            mx = fmaxf(mx, Hs[m*65 + r]);
        }
        mx = fmaxf(mx, __shfl_xor_sync(0xffffffff, mx, 1));
        mx = fmaxf(mx, __shfl_xor_sync(0xffffffff, mx, 2));
        float s = 0.f;
        for (int i = 0; i < 128; i++) {
            int m = part*128 + i;
            float v = expf(Hs[m*65 + r] - mx);
            Hs[m*65 + r] = v;
            s += v;
        }
        s += __shfl_xor_sync(0xffffffff, s, 1);
        s += __shfl_xor_sync(0xffffffff, s, 2);
        if (part == 0) { mxs[r] = mx; invs[r] = 1.0f / s; }
    }
    __syncthreads();

    // Phase 3: multiply by inv * gate (coalesced gate read)
    for (int ii = 0; ii < 128; ii++) {
        int idx = ii*256 + t;
        int l = idx >> 9, m = idx & 511;
        float gate = g_gate[zbase + (size_t)(l0 + l)*512 + m];
        Hs[m*65 + l] *= invs[l] * gate;
    }
    __syncthreads();

    // Phase 4: A@V
    float acc2[4][4];
#pragma unroll
    for (int i = 0; i < 4; i++)
#pragma unroll
        for (int j = 0; j < 4; j++) acc2[i][j] = 0.f;
    const float* vb = qkv + (size_t)b*NSEQ*3*NDIM + 2*NDIM + hd;
    for (int mt = 0; mt < 8; mt++) {
        int m0g = mt * 64;
#pragma unroll
        for (int i = 0; i < 16; i++) {
            int idx = t + i*256;
            int c = idx & 63, r = idx >> 6;
            Vs[r*65 + c] = vb[(size_t)(m0g + r)*(3*NDIM) + c*16];
        }
        __syncthreads();
#pragma unroll 4
        for (int mloc = 0; mloc < 64; mloc++) {
            int m = m0g + mloc;
            float a[4], vv[4];
#pragma unroll
            for (int i = 0; i < 4; i++) a[i]  = Hs[m*65 + ty*4 + i];
#pragma unroll
            for (int j = 0; j < 4; j++) vv[j] = Vs[mloc*65 + tx*4 + j];
#pragma unroll
            for (int i = 0; i < 4; i++)
#pragma unroll
                for (int j = 0; j < 4; j++) acc2[i][j] += a[i]*vv[j];
        }
        __syncthreads();
    }
#pragma unroll
    for (int i = 0; i < 4; i++) {
        int l = l0 + ty*4 + i;
#pragma unroll
        for (int j = 0; j < 4; j++) {
            int k = tx*4 + j;
            g_vatt[(size_t)(b*NSEQ + l)*NDIM + k*16 + hd] = acc2[i][j];
        }
    }
}

// ---------------- persistent fused e-out ----------------
// Block per (b,l): stages weights once, loops over 8 groups of 64 edge rows.
#define EOUT_W1   0
#define EOUT_W2   8448
#define EOUT_WOE  17152
#define EOUT_HROW 18176
#define EOUT_XS   26368
#define EOUT_XSN  30528
#define EOUT_HS   34880
#define EOUT_PAR  43328
#define EOUT_SMEM_FLOATS 43840
__global__ void __launch_bounds__(256) eout_kernel(
    const float* __restrict__ e,
    const float* __restrict__ WOe, const float* __restrict__ bOe,
    const float* __restrict__ lng, const float* __restrict__ lnb,
    const float* __restrict__ W1, const float* __restrict__ b1,
    const float* __restrict__ W2, const float* __restrict__ b2,
    float* __restrict__ eout)
{
    extern __shared__ float sm[];
    float* W1s  = sm + EOUT_W1;    // [64][132] tf32
    float* W2s  = sm + EOUT_W2;    // [128][68] tf32
    float* WOes = sm + EOUT_WOE;   // [16][64]
    float* Hrow = sm + EOUT_HROW;  // [16][512]
    float* xs   = sm + EOUT_XS;    // [64][65]
    float* xsn  = sm + EOUT_XSN;   // [64][68] tf32
    float* hs   = sm + EOUT_HS;    // [64][132] tf32
    float* sbOe = sm + EOUT_PAR;   // 64
    float* sge  = sbOe + 64;       // 64
    float* sbe  = sge  + 64;       // 64
    float* sb1  = sbe  + 64;       // 128
    float* sb2  = sb1  + 128;      // 64
    float* smu  = sb2  + 64;       // 64
    float* srs  = smu  + 64;       // 64

    int t = threadIdx.x;
    int bid = blockIdx.x;          // (b, l)
    int b_ = bid >> 9;
    int l  = bid & 511;

    // stage weights once
    for (int i = t; i < 8192; i += 256) {
        W1s[(i >> 7)*132 + (i & 127)] = f2tf(W1[i]);
        W2s[(i >> 6)*68  + (i & 63)]  = f2tf(W2[i]);
    }
    for (int i = t; i < 1024; i += 256) WOes[i] = WOe[i];
    // whole H row for this (b,l): [hd][m]
    for (int i = t; i < 8192; i += 256) {
        int hd = i >> 9, m = i & 511;
        Hrow[i] = g_H[((size_t)(b_*HEADS + hd))*NN + (size_t)l*512 + m];
    }
    if (t < 64) { sbOe[t] = bOe[t]; sge[t] = lng[t]; sbe[t] = lnb[t]; sb2[t] = b2[t]; }
    if (t >= 64 && t < 192) sb1[t - 64] = b1[t - 64];
    __syncthreads();

    int lane = t & 31;
    int w = t >> 5;
    int wm = w & 3;
    int wn = w >> 2;
    int qr = lane >> 2, qc = lane & 3;
    int tx = t & 15, ty = t >> 4;

    for (int g = 0; g < 8; g++) {
        int m0 = g * 64;
        size_t row0 = (size_t)bid * 512 + m0;

        // Phase A: xs = H@WOe + bOe + e
        {
            float acc[4][4];
#pragma unroll
            for (int i = 0; i < 4; i++)
#pragma unroll
                for (int j = 0; j < 4; j++) acc[i][j] = 0.f;
#pragma unroll
            for (int hd = 0; hd < 16; hd++) {
                float a[4], wv[4];
#pragma unroll
                for (int i = 0; i < 4; i++) a[i] = Hrow[hd*512 + m0 + ty*4 + i];
#pragma unroll
                for (int j = 0; j < 4; j++) wv[j] = WOes[hd*64 + tx*4 + j];
#pragma unroll
                for (int i = 0; i < 4; i++)
#pragma unroll
                    for (int j = 0; j < 4; j++) acc[i][j] += a[i]*wv[j];
            }
#pragma unroll
            for (int i = 0; i < 4; i++) {
                int r = ty*4 + i;
                float4 ev = *(const float4*)&e[(row0 + r)*64 + tx*4];
                xs[r*65 + tx*4 + 0] = acc[i][0] + sbOe[tx*4+0] + ev.x;
                xs[r*65 + tx*4 + 1] = acc[i][1] + sbOe[tx*4+1] + ev.y;
                xs[r*65 + tx*4 + 2] = acc[i][2] + sbOe[tx*4+2] + ev.z;
                xs[r*65 + tx*4 + 3] = acc[i][3] + sbOe[tx*4+3] + ev.w;
            }
        }
        __syncthreads();

        // Phase B: LN stats
        {
            int r = t >> 2, part = t & 3;
            float lv[16]; float s = 0.f;
#pragma unroll
            for (int k = 0; k < 16; k++) { lv[k] = xs[r*65 + part*16 + k]; s += lv[k]; }
            s += __shfl_xor_sync(0xffffffff, s, 1);
            s += __shfl_xor_sync(0xffffffff, s, 2);
            float mu = s * (1.0f/64.0f);
            float q = 0.f;
#pragma unroll
            for (int k = 0; k < 16; k++) { float d = lv[k]-mu; q += d*d; }
            q += __shfl_xor_sync(0xffffffff, q, 1);
            q += __shfl_xor_sync(0xffffffff, q, 2);
            if (part == 0) { smu[r] = mu; srs[r] = rsqrtf(q*(1.0f/64.0f) + 1e-5f); }
        }
        __syncthreads();

        // Phase B2: xsn = tf32(LN(xs))
#pragma unroll
        for (int i = 0; i < 16; i++) {
            int idx = t + i*256;
            int r = idx >> 6, k = idx & 63;
            xsn[r*68 + k] = f2tf((xs[r*65 + k] - smu[r]) * srs[r] * sge[k] + sbe[k]);
        }
        __syncthreads();

        // Phase C (mma): hidden = elu( xsn @ W1 + b1 )
        {
            float acc[8][4];
#pragma unroll
            for (int j = 0; j < 8; j++)
#pragma unroll
                for (int k = 0; k < 4; k++) acc[j][k] = 0.f;
#pragma unroll
            for (int k8 = 0; k8 < 8; k8++) {
                int k = k8 * 8;
                unsigned af[4];
                int r0 = (wm*16 + qr)*68 + k + qc;
                af[0] = __float_as_uint(xsn[r0]);
                af[1] = __float_as_uint(xsn[r0 + 8*68]);
                af[2] = __float_as_uint(xsn[r0 + 4]);
                af[3] = __float_as_uint(xsn[r0 + 8*68 + 4]);
#pragma unroll
                for (int nt = 0; nt < 8; nt++) {
                    int c0 = (k + qc)*132 + wn*64 + nt*8 + qr;
                    unsigned bf[2];
                    bf[0] = __float_as_uint(W1s[c0]);
                    bf[1] = __float_as_uint(W1s[c0 + 4*132]);
                    mma_tf32(acc[nt], af, bf);
                }
            }
#pragma unroll
            for (int nt = 0; nt < 8; nt++) {
                int n = wn*64 + nt*8 + qc*2;
                int mA = wm*16 + qr, mB = mA + 8;
                float v0 = acc[nt][0] + sb1[n];
                float v1 = acc[nt][1] + sb1[n+1];
                float v2 = acc[nt][2] + sb1[n];
                float v3 = acc[nt][3] + sb1[n+1];
                v0 = v0 > 0.f ? v0 : expm1f(v0);
                v1 = v1 > 0.f ? v1 : expm1f(v1);
                v2 = v2 > 0.f ? v2 : expm1f(v2);
                v3 = v3 > 0.f ? v3 : expm1f(v3);
                hs[mA*132 + n]     = f2tf(v0);
                hs[mA*132 + n + 1] = f2tf(v1);
                hs[mB*132 + n]     = f2tf(v2);
                hs[mB*132 + n + 1] = f2tf(v3);
            }
        }
        __syncthreads();

        // Phase E (mma): out = hs @ W2 + b2 + xs
        {
            float acc[4][4];
#pragma unroll
            for (int j = 0; j < 4; j++)
#pragma unroll
                for (int k = 0; k < 4; k++) acc[j][k] = 0.f;
#pragma unroll
            for (int k8 = 0; k8 < 16; k8++) {
                int k = k8 * 8;
                unsigned af[4];
                int r0 = (wm*16 + qr)*132 + k + qc;
                af[0] = __float_as_uint(hs[r0]);
                af[1] = __float_as_uint(hs[r0 + 8*132]);
                af[2] = __float_as_uint(hs[r0 + 4]);
                af[3] = __float_as_uint(hs[r0 + 8*132 + 4]);
#pragma unroll
                for (int nt = 0; nt < 4; nt++) {
                    int c0 = (k + qc)*68 + wn*32 + nt*8 + qr;
                    unsigned bf[2];
                    bf[0] = __float_as_uint(W2s[c0]);
                    bf[1] = __float_as_uint(W2s[c0 + 4*68]);
                    mma_tf32(acc[nt], af, bf);
                }
            }
#pragma unroll
            for (int nt = 0; nt < 4; nt++) {
                int n = wn*32 + nt*8 + qc*2;
                int mA = wm*16 + qr, mB = mA + 8;
                float2 oA, oB;
                oA.x = acc[nt][0] + sb2[n]   + xs[mA*65 + n];
                oA.y = acc[nt][1] + sb2[n+1] + xs[mA*65 + n + 1];
                oB.x = acc[nt][2] + sb2[n]   + xs[mB*65 + n];
                oB.y = acc[nt][3] + sb2[n+1] + xs[mB*65 + n + 1];
                *(float2*)&eout[(row0 + mA)*64 + n] = oA;
                *(float2*)&eout[(row0 + mB)*64 + n] = oB;
            }
        }
        __syncthreads();
    }
}

// ---------------- host launcher ----------------
extern "C" void kernel_launch(void* const* d_in, const int* in_sizes, int n_in,
                              void* d_out, int out_size)
{
    const float* h        = (const float*)d_in[0];
    const float* e        = (const float*)d_in[1];
    const float* ln_h_g   = (const float*)d_in[2];
    const float* ln_h_b   = (const float*)d_in[3];
    const float* ln_e_g   = (const float*)d_in[4];
    const float* ln_e_b   = (const float*)d_in[5];
    const float* W_E      = (const float*)d_in[6];
    const float* b_E      = (const float*)d_in[7];
    const float* W_QKV    = (const float*)d_in[8];
    const float* b_QKV    = (const float*)d_in[9];
    const float* W_G      = (const float*)d_in[10];
    const float* b_G      = (const float*)d_in[11];
    const float* W_Oh     = (const float*)d_in[12];
    const float* b_Oh     = (const float*)d_in[13];
    const float* ffn_ln_h_g = (const float*)d_in[14];
    const float* ffn_ln_h_b = (const float*)d_in[15];
    const float* W_h1     = (const float*)d_in[16];
    const float* b_h1     = (const float*)d_in[17];
    const float* W_h2     = (const float*)d_in[18];
    const float* b_h2     = (const float*)d_in[19];
    const float* W_Oe     = (const float*)d_in[20];
    const float* b_Oe     = (const float*)d_in[21];
    const float* ffn_ln_e_g = (const float*)d_in[22];
    const float* ffn_ln_e_b = (const float*)d_in[23];
    const float* W_e1     = (const float*)d_in[24];
    const float* b_e1     = (const float*)d_in[25];
    const float* W_e2     = (const float*)d_in[26];
    const float* b_e2     = (const float*)d_in[27];

    float* out_h = (float*)d_out;
    float* out_e = out_h + H_OUT_ELEMS;

    float *p_hln, *p_qkv, *p_vatt, *p_h1, *p_h2, *p_act;
    cudaGetSymbolAddress((void**)&p_hln,  g_hln);
    cudaGetSymbolAddress((void**)&p_qkv,  g_qkv);
    cudaGetSymbolAddress((void**)&p_vatt, g_vatt);
    cudaGetSymbolAddress((void**)&p_h1,   g_h1);
    cudaGetSymbolAddress((void**)&p_h2,   g_h2);
    cudaGetSymbolAddress((void**)&p_act,  g_act);

    // h path pre-attention
    ln1024_kernel<<<BN, 256>>>(h, ln_h_g, ln_h_b, p_hln);
    gemm_tc_kernel<<<dim3(3*NDIM/128, BN/128), 256>>>(p_hln, W_QKV, b_QKV, nullptr, p_qkv,
                                                      BN, 3*NDIM, NDIM, 0);
    // e path: LN + E/G projections
    eg_kernel<<<(unsigned)(EROWS/64), 256>>>(e, ln_e_g, ln_e_b, W_E, b_E, W_G, b_G);
    // fused attention (qk + softmax + av)
    cudaFuncSetAttribute(av2_kernel, cudaFuncAttributeMaxDynamicSharedMemorySize,
                         AV2_SMEM * 4);
    av2_kernel<<<dim3(8, BHN), 256, AV2_SMEM * 4>>>(p_qkv);
    // h path post-attention
    gemm_tc_kernel<<<dim3(NDIM/128, BN/128), 256>>>(p_vatt, W_Oh, b_Oh, h, p_h1,
                                                    BN, NDIM, NDIM, 0);
    ln1024_kernel<<<BN, 256>>>(p_h1, ffn_ln_h_g, ffn_ln_h_b, p_h2);
    gemm_tc_kernel<<<dim3(FFN_H/128, BN/128), 256>>>(p_h2, W_h1, b_h1, nullptr, p_act,
                                                     BN, FFN_H, NDIM, 1);
    gemm_tc_kernel<<<dim3(NDIM/128, BN/128), 256>>>(p_act, W_h2, b_h2, p_h1, out_h,
                                                    BN, NDIM, FFN_H, 0);
    // fused e output path (persistent, weights staged once per (b,l))
    cudaFuncSetAttribute(eout_kernel, cudaFuncAttributeMaxDynamicSharedMemorySize,
                         EOUT_SMEM_FLOATS * 4);
    eout_kernel<<<BN, 256, EOUT_SMEM_FLOATS * 4>>>(
        e, W_Oe, b_Oe, ffn_ln_e_g, ffn_ln_e_b, W_e1, b_e1, W_e2, b_e2, out_e);
}

// round 6
// speedup vs baseline: 2.1864x; 1.0497x over previous
#include <cuda_runtime.h>
#include <cuda_bf16.h>
#include <math.h>

// ---------------- problem constants ----------------
#define BATCH   4
#define NSEQ    512
#define NDIM    1024
#define EDIM    64
#define HEADS   16
#define DOTD    64
#define FFN_H   2048
#define FFN_E   128
#define BN      (BATCH*NSEQ)          // 2048 token rows
#define NN      (NSEQ*NSEQ)           // 262144 per batch
#define BHN     (BATCH*HEADS)         // 64
#define EROWS   ((size_t)BATCH*NSEQ*NSEQ) // 1048576 edge rows
#define H_OUT_ELEMS (BN*NDIM)         // 2097152

// ---------------- scratch (device globals; no allocs allowed) ----------------
__device__ float g_hln [BN*NDIM];
__device__ float g_qkv [BN*3*NDIM];
__device__ float g_E   [(size_t)BHN*NN];   // (b*16+h, l*512+m)
__device__ float g_gate[(size_t)BHN*NN];
__device__ float g_H   [(size_t)BHN*NN];   // H_hat = clip(A)+E
__device__ float g_vatt[BN*NDIM];
__device__ float g_h1  [BN*NDIM];          // h after O_h + residual
__device__ float g_h2  [BN*NDIM];          // LN of g_h1
__device__ float g_act [BN*FFN_H];

// ---------------- LayerNorm over 1024 ----------------
__global__ void __launch_bounds__(256) ln1024_kernel(
    const float* __restrict__ x, const float* __restrict__ g,
    const float* __restrict__ b, float* __restrict__ y)
{
    int row = blockIdx.x, t = threadIdx.x;
    const float* xr = x + (size_t)row * NDIM;
    float v[4]; float s = 0.f;
#pragma unroll
    for (int i = 0; i < 4; i++) { v[i] = xr[t + i*256]; s += v[i]; }
    __shared__ float red[8];
    int lane = t & 31, w = t >> 5;
#pragma unroll
    for (int o = 16; o; o >>= 1) s += __shfl_xor_sync(0xffffffff, s, o);
    if (lane == 0) red[w] = s;
    __syncthreads();
    float tot = 0.f;
#pragma unroll
    for (int i = 0; i < 8; i++) tot += red[i];
    float mu = tot * (1.0f/NDIM);
    __syncthreads();
    float q = 0.f;
#pragma unroll
    for (int i = 0; i < 4; i++) { float d = v[i]-mu; q += d*d; }
#pragma unroll
    for (int o = 16; o; o >>= 1) q += __shfl_xor_sync(0xffffffff, q, o);
    if (lane == 0) red[w] = q;
    __syncthreads();
    float qt = 0.f;
#pragma unroll
    for (int i = 0; i < 8; i++) qt += red[i];
    float rs = rsqrtf(qt * (1.0f/NDIM) + 1e-5f);
    float* yr = y + (size_t)row * NDIM;
#pragma unroll
    for (int i = 0; i < 4; i++) {
        int c = t + i*256;
        yr[c] = (v[i]-mu)*rs*g[c] + b[c];
    }
}

// ---------------- tf32 helpers ----------------
__device__ __forceinline__ float f2tf(float x) {
    unsigned r;
    asm("cvt.rna.tf32.f32 %0, %1;" : "=r"(r) : "f"(x));
    return __uint_as_float(r);
}

__device__ __forceinline__ void mma_tf32(float* c, const unsigned* a, const unsigned* b) {
    asm volatile(
        "mma.sync.aligned.m16n8k8.row.col.f32.tf32.tf32.f32 "
        "{%0,%1,%2,%3}, {%4,%5,%6,%7}, {%8,%9}, {%0,%1,%2,%3};\n"
        : "+f"(c[0]), "+f"(c[1]), "+f"(c[2]), "+f"(c[3])
        : "r"(a[0]), "r"(a[1]), "r"(a[2]), "r"(a[3]), "r"(b[0]), "r"(b[1]));
}

// ---------------- tf32 tensor-core GEMM: C = act(A@W + bias) (+res) ----------------
#define AS_LD 17
#define BS_LD 132
__global__ void __launch_bounds__(256) gemm_tc_kernel(
    const float* __restrict__ A, const float* __restrict__ W,
    const float* __restrict__ bias, const float* __restrict__ res,
    float* __restrict__ C, int M, int N, int K, int act)
{
    __shared__ float As[2][128*AS_LD];
    __shared__ float Bs[2][16*BS_LD];

    int t = threadIdx.x;
    int lane = t & 31;
    int w = t >> 5;
    int wm = w & 3;
    int wn = w >> 2;
    int qr = lane >> 2;
    int qc = lane & 3;
    int n0 = blockIdx.x * 128, m0 = blockIdx.y * 128;

    int arow = t >> 1;
    int acol = (t & 1) * 8;
    int brow = t >> 4;
    int bcol = (t & 15) * 8;

    const float* Aptr = A + (size_t)(m0 + arow)*K + acol;
    const float* Bptr = W + (size_t)brow*N + n0 + bcol;

    float acc[2][8][4];
#pragma unroll
    for (int i = 0; i < 2; i++)
#pragma unroll
        for (int j = 0; j < 8; j++)
#pragma unroll
            for (int k = 0; k < 4; k++) acc[i][j][k] = 0.f;

    int KT = K / 16;
    float4 ra0, ra1, rb0, rb1;
    ra0 = *(const float4*)(Aptr + 0);
    ra1 = *(const float4*)(Aptr + 4);
    rb0 = *(const float4*)(Bptr + 0);
    rb1 = *(const float4*)(Bptr + 4);
    {
        float* as = As[0]; float* bs = Bs[0];
        int sa = arow*AS_LD + acol;
        as[sa+0]=f2tf(ra0.x); as[sa+1]=f2tf(ra0.y); as[sa+2]=f2tf(ra0.z); as[sa+3]=f2tf(ra0.w);
        as[sa+4]=f2tf(ra1.x); as[sa+5]=f2tf(ra1.y); as[sa+6]=f2tf(ra1.z); as[sa+7]=f2tf(ra1.w);
        int sb = brow*BS_LD + bcol;
        bs[sb+0]=f2tf(rb0.x); bs[sb+1]=f2tf(rb0.y); bs[sb+2]=f2tf(rb0.z); bs[sb+3]=f2tf(rb0.w);
        bs[sb+4]=f2tf(rb1.x); bs[sb+5]=f2tf(rb1.y); bs[sb+6]=f2tf(rb1.z); bs[sb+7]=f2tf(rb1.w);
    }
    __syncthreads();

    for (int kt = 0; kt < KT; kt++) {
        int cur = kt & 1;
        if (kt + 1 < KT) {
            int k0 = (kt + 1) * 16;
            ra0 = *(const float4*)(Aptr + k0);
            ra1 = *(const float4*)(Aptr + k0 + 4);
            rb0 = *(const float4*)(Bptr + (size_t)k0*N);
            rb1 = *(const float4*)(Bptr + (size_t)k0*N + 4);
        }
        const float* as = As[cur];
        const float* bs = Bs[cur];
#pragma unroll
        for (int ks = 0; ks < 2; ks++) {
            int k = ks * 8;
            unsigned af[2][4];
#pragma unroll
            for (int mt = 0; mt < 2; mt++) {
                int r0 = (wm*32 + mt*16 + qr) * AS_LD + k + qc;
                af[mt][0] = __float_as_uint(as[r0]);
                af[mt][1] = __float_as_uint(as[r0 + 8*AS_LD]);
                af[mt][2] = __float_as_uint(as[r0 + 4]);
                af[mt][3] = __float_as_uint(as[r0 + 8*AS_LD + 4]);
            }
            unsigned bf[8][2];
#pragma unroll
            for (int nt = 0; nt < 8; nt++) {
                int c0 = (k + qc)*BS_LD + wn*64 + nt*8 + qr;
                bf[nt][0] = __float_as_uint(bs[c0]);
                bf[nt][1] = __float_as_uint(bs[c0 + 4*BS_LD]);
            }
#pragma unroll
            for (int mt = 0; mt < 2; mt++)
#pragma unroll
                for (int nt = 0; nt < 8; nt++)
                    mma_tf32(acc[mt][nt], af[mt], bf[nt]);
        }
        if (kt + 1 < KT) {
            float* asw = As[cur ^ 1]; float* bsw = Bs[cur ^ 1];
            int sa = arow*AS_LD + acol;
            asw[sa+0]=f2tf(ra0.x); asw[sa+1]=f2tf(ra0.y); asw[sa+2]=f2tf(ra0.z); asw[sa+3]=f2tf(ra0.w);
            asw[sa+4]=f2tf(ra1.x); asw[sa+5]=f2tf(ra1.y); asw[sa+6]=f2tf(ra1.z); asw[sa+7]=f2tf(ra1.w);
            int sb = brow*BS_LD + bcol;
            bsw[sb+0]=f2tf(rb0.x); bsw[sb+1]=f2tf(rb0.y); bsw[sb+2]=f2tf(rb0.z); bsw[sb+3]=f2tf(rb0.w);
            bsw[sb+4]=f2tf(rb1.x); bsw[sb+5]=f2tf(rb1.y); bsw[sb+6]=f2tf(rb1.z); bsw[sb+7]=f2tf(rb1.w);
        }
        __syncthreads();
    }

#pragma unroll
    for (int mt = 0; mt < 2; mt++) {
        int mA = m0 + wm*32 + mt*16 + qr;
        int mB = mA + 8;
#pragma unroll
        for (int nt = 0; nt < 8; nt++) {
            int n = n0 + wn*64 + nt*8 + qc*2;
            float b0 = bias[n], b1 = bias[n + 1];
            float v0 = acc[mt][nt][0] + b0;
            float v1 = acc[mt][nt][1] + b1;
            float v2 = acc[mt][nt][2] + b0;
            float v3 = acc[mt][nt][3] + b1;
            if (act) {
                v0 = v0 > 0.f ? v0 : expm1f(v0);
                v1 = v1 > 0.f ? v1 : expm1f(v1);
                v2 = v2 > 0.f ? v2 : expm1f(v2);
                v3 = v3 > 0.f ? v3 : expm1f(v3);
            }
            if (res) {
                const float* rA = res + (size_t)mA*N + n;
                const float* rB = res + (size_t)mB*N + n;
                v0 += rA[0]; v1 += rA[1];
                v2 += rB[0]; v3 += rB[1];
            }
            float2 oA; oA.x = v0; oA.y = v1;
            float2 oB; oB.x = v2; oB.y = v3;
            *(float2*)(C + (size_t)mA*N + n) = oA;
            *(float2*)(C + (size_t)mB*N + n) = oB;
        }
    }
}

// ---------------- e -> LN -> E proj, sigmoid(G proj) ----------------
__global__ void __launch_bounds__(256) eg_kernel(
    const float* __restrict__ e,
    const float* __restrict__ lng, const float* __restrict__ lnb,
    const float* __restrict__ WE, const float* __restrict__ bE,
    const float* __restrict__ WG, const float* __restrict__ bG)
{
    __shared__ float xs[64*65];
    __shared__ float wE[64*16], wG[64*16];
    __shared__ float ob[32*65];
    __shared__ float sg[64], sb[64], sbE[16], sbG[16];
    int t = threadIdx.x;
    size_t row0 = (size_t)blockIdx.x * 64;

    for (int i = t; i < 1024; i += 256) { wE[i] = WE[i]; wG[i] = WG[i]; }
    if (t < 64) { sg[t] = lng[t]; sb[t] = lnb[t]; }
    if (t < 16) { sbE[t] = bE[t]; sbG[t] = bG[t]; }
#pragma unroll
    for (int i = 0; i < 16; i++) {
        int idx = t + i*256;
        int r = idx >> 6, c = idx & 63;
        xs[r*65 + c] = e[row0*64 + idx];
    }
    __syncthreads();
    {
        int r = t >> 2, part = t & 3;
        float lv[16]; float s = 0.f;
#pragma unroll
        for (int k = 0; k < 16; k++) { lv[k] = xs[r*65 + part*16 + k]; s += lv[k]; }
        s += __shfl_xor_sync(0xffffffff, s, 1);
        s += __shfl_xor_sync(0xffffffff, s, 2);
        float mu = s * (1.0f/64.0f);
        float q = 0.f;
#pragma unroll
        for (int k = 0; k < 16; k++) { float d = lv[k]-mu; q += d*d; }
        q += __shfl_xor_sync(0xffffffff, q, 1);
        q += __shfl_xor_sync(0xffffffff, q, 2);
        float rsg = rsqrtf(q * (1.0f/64.0f) + 1e-5f);
#pragma unroll
        for (int k = 0; k < 16; k++) {
            int c = part*16 + k;
            xs[r*65 + c] = (lv[k]-mu)*rsg*sg[c] + sb[c];
        }
    }
    __syncthreads();
    {
        int o = t & 31, rg = t >> 5;
        bool isE = (o < 16);
        int oo = isE ? o : o - 16;
        const float* wp = isE ? wE : wG;
#pragma unroll
        for (int i = 0; i < 8; i++) {
            int rr = rg*8 + i;
            float a = 0.f;
#pragma unroll
            for (int k = 0; k < 64; k++) a += xs[rr*65 + k] * wp[k*16 + oo];
            a += isE ? sbE[oo] : sbG[oo];
            if (!isE) a = 1.0f / (1.0f + expf(-a));
            ob[o*65 + rr] = a;
        }
    }
    __syncthreads();
    int b_ = (int)(row0 >> 18);
    int rem = (int)(row0 & (NN - 1));
    int l = rem >> 9, m0 = rem & 511;
#pragma unroll
    for (int i = 0; i < 8; i++) {
        int idx = t + i*256;
        int o = idx >> 6, rr = idx & 63;
        float val = ob[o*65 + rr];
        int hd = o & 15;
        size_t dst = ((size_t)(b_*HEADS + hd))*NN + (size_t)l*512 + m0 + rr;
        if (o < 16) g_E[dst] = val; else g_gate[dst] = val;
    }
}

// ---------------- fused attention v2 (tf32 mma):
//   QK^T+clip+E -> H (gmem + smem), softmax*gate in smem, A@V -> vatt
// Block: 64 l-rows x 1 head. Grid (8, 64). 256 threads (8 warps).
// smem (floats): Hs[512][68], Qs[64][68], Ks[64][68], Vs[64][68], invs[64]
#define AV2_HS   0
#define AV2_QS   34816
#define AV2_KS   39168
#define AV2_VS   43520
#define AV2_INV  47872
#define AV2_SMEM 47936
__global__ void __launch_bounds__(256) av2_kernel(const float* __restrict__ qkv)
{
    extern __shared__ float sm[];
    float* Hs  = sm + AV2_HS;    // [m 0..511][l 0..63] ld 68
    float* Qs  = sm + AV2_QS;    // [l][d] ld 68 (A row-major)
    float* Ks  = sm + AV2_KS;    // [d][m] ld 68 (B col-major)
    float* Vs  = sm + AV2_VS;    // [m][k] ld 68 (B col-major)
    float* invs= sm + AV2_INV;

    int t = threadIdx.x;
    int l0 = blockIdx.x * 64;
    int z = blockIdx.y;
    int b = z >> 4, hd = z & 15;
    int lane = t & 31;
    int w = t >> 5;
    int wm = w & 3;             // l-tile of 16
    int wh = w >> 2;            // m/n half of 32
    int qr = lane >> 2, qc = lane & 3;
    size_t zbase = (size_t)z * NN;
    const float* qb = qkv + (size_t)b*NSEQ*3*NDIM + hd;

    // load Q strip [l][d] (tf32)
#pragma unroll
    for (int i = 0; i < 16; i++) {
        int idx = t + i*256;
        int lloc = idx >> 6, d = idx & 63;
        Qs[lloc*68 + d] = f2tf(qb[(size_t)(l0 + lloc)*(3*NDIM) + d*16]);
    }

    // Phase 1: per m-tile, mma QK^T, scale+clip, +E; write g_H and Hs
    for (int mt = 0; mt < 8; mt++) {
        int m0g = mt * 64;
#pragma unroll
        for (int i = 0; i < 16; i++) {
            int idx = t + i*256;
            int mloc = idx >> 6, d = idx & 63;
            Ks[d*68 + mloc] = f2tf(qb[(size_t)(m0g + mloc)*(3*NDIM) + NDIM + d*16]);
        }
        __syncthreads();

        float acc[4][4];
#pragma unroll
        for (int j = 0; j < 4; j++)
#pragma unroll
            for (int k = 0; k < 4; k++) acc[j][k] = 0.f;
#pragma unroll
        for (int k8 = 0; k8 < 8; k8++) {
            int k = k8 * 8;
            unsigned af[4];
            int r0 = (wm*16 + qr)*68 + k + qc;
            af[0] = __float_as_uint(Qs[r0]);
            af[1] = __float_as_uint(Qs[r0 + 8*68]);
            af[2] = __float_as_uint(Qs[r0 + 4]);
            af[3] = __float_as_uint(Qs[r0 + 8*68 + 4]);
#pragma unroll
            for (int nt = 0; nt < 4; nt++) {
                int c0 = (k + qc)*68 + wh*32 + nt*8 + qr;
                unsigned bf[2];
                bf[0] = __float_as_uint(Ks[c0]);
                bf[1] = __float_as_uint(Ks[c0 + 4*68]);
                mma_tf32(acc[nt], af, bf);
            }
        }
        // epilogue: scale, clip, +E -> g_H + Hs
#pragma unroll
        for (int nt = 0; nt < 4; nt++) {
            int mcol = wh*32 + nt*8 + qc*2;
            int lA = wm*16 + qr, lB = lA + 8;
            size_t roA = zbase + (size_t)(l0 + lA)*512 + m0g + mcol;
            size_t roB = zbase + (size_t)(l0 + lB)*512 + m0g + mcol;
            float2 eA = *(const float2*)&g_E[roA];
            float2 eB = *(const float2*)&g_E[roB];
            float2 hA, hB;
            hA.x = fminf(fmaxf(acc[nt][0]*0.125f, -5.f), 5.f) + eA.x;
            hA.y = fminf(fmaxf(acc[nt][1]*0.125f, -5.f), 5.f) + eA.y;
            hB.x = fminf(fmaxf(acc[nt][2]*0.125f, -5.f), 5.f) + eB.x;
            hB.y = fminf(fmaxf(acc[nt][3]*0.125f, -5.f), 5.f) + eB.y;
            *(float2*)&g_H[roA] = hA;
            *(float2*)&g_H[roB] = hB;
            int mg = m0g + mcol;
            Hs[(mg+0)*68 + lA] = hA.x;
            Hs[(mg+1)*68 + lA] = hA.y;
            Hs[(mg+0)*68 + lB] = hB.x;
            Hs[(mg+1)*68 + lB] = hB.y;
        }
        __syncthreads();
    }

    // Phase 2: softmax stats per l-row (4 threads/row, interleaved m)
    {
        int r = t >> 2, part = t & 3;
        float mx = -1e30f;
        for (int i = 0; i < 128; i++) {
            int m = i*4 + part;
            mx = fmaxf(mx, Hs[m*68 + r]);
        }
        mx = fmaxf(mx, __shfl_xor_sync(0xffffffff, mx, 1));
        mx = fmaxf(mx, __shfl_xor_sync(0xffffffff, mx, 2));
        float s = 0.f;
        for (int i = 0; i < 128; i++) {
            int m = i*4 + part;
            float v = expf(Hs[m*68 + r] - mx);
            Hs[m*68 + r] = v;
            s += v;
        }
        s += __shfl_xor_sync(0xffffffff, s, 1);
        s += __shfl_xor_sync(0xffffffff, s, 2);
        if (part == 0) invs[r] = 1.0f / s;
    }
    __syncthreads();

    // Phase 3: multiply by inv * gate (tf32 for mma A-operand)
    for (int ii = 0; ii < 128; ii++) {
        int idx = ii*256 + t;
        int l = idx >> 9, m = idx & 511;
        float gate = g_gate[zbase + (size_t)(l0 + l)*512 + m];
        Hs[m*68 + l] = f2tf(Hs[m*68 + l] * invs[l] * gate);
    }
    __syncthreads();

    // Phase 4: A@V via mma, K = 512 (8 chunks of 64)
    float acc2[4][4];
#pragma unroll
    for (int j = 0; j < 4; j++)
#pragma unroll
        for (int k = 0; k < 4; k++) acc2[j][k] = 0.f;
    const float* vb = qkv + (size_t)b*NSEQ*3*NDIM + 2*NDIM + hd;
    for (int mt = 0; mt < 8; mt++) {
        int m0g = mt * 64;
#pragma unroll
        for (int i = 0; i < 16; i++) {
            int idx = t + i*256;
            int mloc = idx >> 6, kout = idx & 63;
            Vs[mloc*68 + kout] = f2tf(vb[(size_t)(m0g + mloc)*(3*NDIM) + kout*16]);
        }
        __syncthreads();
#pragma unroll
        for (int k8 = 0; k8 < 8; k8++) {
            int kk = k8 * 8;
            unsigned af[4];
            int a0 = (m0g + kk + qc)*68 + wm*16 + qr;
            af[0] = __float_as_uint(Hs[a0]);
            af[1] = __float_as_uint(Hs[a0 + 8]);
            af[2] = __float_as_uint(Hs[a0 + 4*68]);
            af[3] = __float_as_uint(Hs[a0 + 4*68 + 8]);
#pragma unroll
            for (int nt = 0; nt < 4; nt++) {
                int c0 = (kk + qc)*68 + wh*32 + nt*8 + qr;
                unsigned bf[2];
                bf[0] = __float_as_uint(Vs[c0]);
                bf[1] = __float_as_uint(Vs[c0 + 4*68]);
                mma_tf32(acc2[nt], af, bf);
            }
        }
        __syncthreads();
    }
#pragma unroll
    for (int nt = 0; nt < 4; nt++) {
        int lA = l0 + wm*16 + qr;
        int lB = lA + 8;
        int kout = wh*32 + nt*8 + qc*2;
        g_vatt[(size_t)(b*NSEQ + lA)*NDIM + (kout+0)*16 + hd] = acc2[nt][0];
        g_vatt[(size_t)(b*NSEQ + lA)*NDIM + (kout+1)*16 + hd] = acc2[nt][1];
        g_vatt[(size_t)(b*NSEQ + lB)*NDIM + (kout+0)*16 + hd] = acc2[nt][2];
        g_vatt[(size_t)(b*NSEQ + lB)*NDIM + (kout+1)*16 + hd] = acc2[nt][3];
    }
}

// ---------------- persistent fused e-out ----------------
#define EOUT_W1   0
#define EOUT_W2   8448
#define EOUT_WOE  17152
#define EOUT_HROW 18176
#define EOUT_XS   26368
#define EOUT_XSN  30528
#define EOUT_HS   34880
#define EOUT_PAR  43328
#define EOUT_SMEM_FLOATS 43840
__global__ void __launch_bounds__(256) eout_kernel(
    const float* __restrict__ e,
    const float* __restrict__ WOe, const float* __restrict__ bOe,
    const float* __restrict__ lng, const float* __restrict__ lnb,
    const float* __restrict__ W1, const float* __restrict__ b1,
    const float* __restrict__ W2, const float* __restrict__ b2,
    float* __restrict__ eout)
{
    extern __shared__ float sm[];
    float* W1s  = sm + EOUT_W1;    // [64][132] tf32
    float* W2s  = sm + EOUT_W2;    // [128][68] tf32
    float* WOes = sm + EOUT_WOE;   // [16][64]
    float* Hrow = sm + EOUT_HROW;  // [16][512]
    float* xs   = sm + EOUT_XS;    // [64][65]
    float* xsn  = sm + EOUT_XSN;   // [64][68] tf32
    float* hs   = sm + EOUT_HS;    // [64][132] tf32
    float* sbOe = sm + EOUT_PAR;   // 64
    float* sge  = sbOe + 64;       // 64
    float* sbe  = sge  + 64;       // 64
    float* sb1  = sbe  + 64;       // 128
    float* sb2  = sb1  + 128;      // 64
    float* smu  = sb2  + 64;       // 64
    float* srs  = smu  + 64;       // 64

    int t = threadIdx.x;
    int bid = blockIdx.x;          // (b, l)
    int b_ = bid >> 9;
    int l  = bid & 511;

    for (int i = t; i < 8192; i += 256) {
        W1s[(i >> 7)*132 + (i & 127)] = f2tf(W1[i]);
        W2s[(i >> 6)*68  + (i & 63)]  = f2tf(W2[i]);
    }
    for (int i = t; i < 1024; i += 256) WOes[i] = WOe[i];
    for (int i = t; i < 8192; i += 256) {
        int hd = i >> 9, m = i & 511;
        Hrow[i] = g_H[((size_t)(b_*HEADS + hd))*NN + (size_t)l*512 + m];
    }
    if (t < 64) { sbOe[t] = bOe[t]; sge[t] = lng[t]; sbe[t] = lnb[t]; sb2[t] = b2[t]; }
    if (t >= 64 && t < 192) sb1[t - 64] = b1[t - 64];
    __syncthreads();

    int lane = t & 31;
    int w = t >> 5;
    int wm = w & 3;
    int wn = w >> 2;
    int qr = lane >> 2, qc = lane & 3;
    int tx = t & 15, ty = t >> 4;

    for (int g = 0; g < 8; g++) {
        int m0 = g * 64;
        size_t row0 = (size_t)bid * 512 + m0;

        // Phase A: xs = H@WOe + bOe + e
        {
            float acc[4][4];
#pragma unroll
            for (int i = 0; i < 4; i++)
#pragma unroll
                for (int j = 0; j < 4; j++) acc[i][j] = 0.f;
#pragma unroll
            for (int hd = 0; hd < 16; hd++) {
                float a[4], wv[4];
#pragma unroll
                for (int i = 0; i < 4; i++) a[i] = Hrow[hd*512 + m0 + ty*4 + i];
#pragma unroll
                for (int j = 0; j < 4; j++) wv[j] = WOes[hd*64 + tx*4 + j];
#pragma unroll
                for (int i = 0; i < 4; i++)
#pragma unroll
                    for (int j = 0; j < 4; j++) acc[i][j] += a[i]*wv[j];
            }
#pragma unroll
            for (int i = 0; i < 4; i++) {
                int r = ty*4 + i;
                float4 ev = *(const float4*)&e[(row0 + r)*64 + tx*4];
                xs[r*65 + tx*4 + 0] = acc[i][0] + sbOe[tx*4+0] + ev.x;
                xs[r*65 + tx*4 + 1] = acc[i][1] + sbOe[tx*4+1] + ev.y;
                xs[r*65 + tx*4 + 2] = acc[i][2] + sbOe[tx*4+2] + ev.z;
                xs[r*65 + tx*4 + 3] = acc[i][3] + sbOe[tx*4+3] + ev.w;
            }
        }
        __syncthreads();

        // Phase B: LN stats
        {
            int r = t >> 2, part = t & 3;
            float lv[16]; float s = 0.f;
#pragma unroll
            for (int k = 0; k < 16; k++) { lv[k] = xs[r*65 + part*16 + k]; s += lv[k]; }
            s += __shfl_xor_sync(0xffffffff, s, 1);
            s += __shfl_xor_sync(0xffffffff, s, 2);
            float mu = s * (1.0f/64.0f);
            float q = 0.f;
#pragma unroll
            for (int k = 0; k < 16; k++) { float d = lv[k]-mu; q += d*d; }
            q += __shfl_xor_sync(0xffffffff, q, 1);
            q += __shfl_xor_sync(0xffffffff, q, 2);
            if (part == 0) { smu[r] = mu; srs[r] = rsqrtf(q*(1.0f/64.0f) + 1e-5f); }
        }
        __syncthreads();

        // Phase B2: xsn = tf32(LN(xs))
#pragma unroll
        for (int i = 0; i < 16; i++) {
            int idx = t + i*256;
            int r = idx >> 6, k = idx & 63;
            xsn[r*68 + k] = f2tf((xs[r*65 + k] - smu[r]) * srs[r] * sge[k] + sbe[k]);
        }
        __syncthreads();

        // Phase C (mma): hidden = elu( xsn @ W1 + b1 )
        {
            float acc[8][4];
#pragma unroll
            for (int j = 0; j < 8; j++)
#pragma unroll
                for (int k = 0; k < 4; k++) acc[j][k] = 0.f;
#pragma unroll
            for (int k8 = 0; k8 < 8; k8++) {
                int k = k8 * 8;
                unsigned af[4];
                int r0 = (wm*16 + qr)*68 + k + qc;
                af[0] = __float_as_uint(xsn[r0]);
                af[1] = __float_as_uint(xsn[r0 + 8*68]);
                af[2] = __float_as_uint(xsn[r0 + 4]);
                af[3] = __float_as_uint(xsn[r0 + 8*68 + 4]);
#pragma unroll
                for (int nt = 0; nt < 8; nt++) {
                    int c0 = (k + qc)*132 + wn*64 + nt*8 + qr;
                    unsigned bf[2];
                    bf[0] = __float_as_uint(W1s[c0]);
                    bf[1] = __float_as_uint(W1s[c0 + 4*132]);
                    mma_tf32(acc[nt], af, bf);
                }
            }
#pragma unroll
            for (int nt = 0; nt < 8; nt++) {
                int n = wn*64 + nt*8 + qc*2;
                int mA = wm*16 + qr, mB = mA + 8;
                float v0 = acc[nt][0] + sb1[n];
                float v1 = acc[nt][1] + sb1[n+1];
                float v2 = acc[nt][2] + sb1[n];
                float v3 = acc[nt][3] + sb1[n+1];
                v0 = v0 > 0.f ? v0 : expm1f(v0);
                v1 = v1 > 0.f ? v1 : expm1f(v1);
                v2 = v2 > 0.f ? v2 : expm1f(v2);
                v3 = v3 > 0.f ? v3 : expm1f(v3);
                hs[mA*132 + n]     = f2tf(v0);
                hs[mA*132 + n + 1] = f2tf(v1);
                hs[mB*132 + n]     = f2tf(v2);
                hs[mB*132 + n + 1] = f2tf(v3);
            }
        }
        __syncthreads();

        // Phase E (mma): out = hs @ W2 + b2 + xs
        {
            float acc[4][4];
#pragma unroll
            for (int j = 0; j < 4; j++)
#pragma unroll
                for (int k = 0; k < 4; k++) acc[j][k] = 0.f;
#pragma unroll
            for (int k8 = 0; k8 < 16; k8++) {
                int k = k8 * 8;
                unsigned af[4];
                int r0 = (wm*16 + qr)*132 + k + qc;
                af[0] = __float_as_uint(hs[r0]);
                af[1] = __float_as_uint(hs[r0 + 8*132]);
                af[2] = __float_as_uint(hs[r0 + 4]);
                af[3] = __float_as_uint(hs[r0 + 8*132 + 4]);
#pragma unroll
                for (int nt = 0; nt < 4; nt++) {
                    int c0 = (k + qc)*68 + wn*32 + nt*8 + qr;
                    unsigned bf[2];
                    bf[0] = __float_as_uint(W2s[c0]);
                    bf[1] = __float_as_uint(W2s[c0 + 4*68]);
                    mma_tf32(acc[nt], af, bf);
                }
            }
#pragma unroll
            for (int nt = 0; nt < 4; nt++) {
                int n = wn*32 + nt*8 + qc*2;
                int mA = wm*16 + qr, mB = mA + 8;
                float2 oA, oB;
                oA.x = acc[nt][0] + sb2[n]   + xs[mA*65 + n];
                oA.y = acc[nt][1] + sb2[n+1] + xs[mA*65 + n + 1];
                oB.x = acc[nt][2] + sb2[n]   + xs[mB*65 + n];
                oB.y = acc[nt][3] + sb2[n+1] + xs[mB*65 + n + 1];
                *(float2*)&eout[(row0 + mA)*64 + n] = oA;
                *(float2*)&eout[(row0 + mB)*64 + n] = oB;
            }
        }
        __syncthreads();
    }
}

// ---------------- host launcher ----------------
extern "C" void kernel_launch(void* const* d_in, const int* in_sizes, int n_in,
                              void* d_out, int out_size)
{
    const float* h        = (const float*)d_in[0];
    const float* e        = (const float*)d_in[1];
    const float* ln_h_g   = (const float*)d_in[2];
    const float* ln_h_b   = (const float*)d_in[3];
    const float* ln_e_g   = (const float*)d_in[4];
    const float* ln_e_b   = (const float*)d_in[5];
    const float* W_E      = (const float*)d_in[6];
    const float* b_E      = (const float*)d_in[7];
    const float* W_QKV    = (const float*)d_in[8];
    const float* b_QKV    = (const float*)d_in[9];
    const float* W_G      = (const float*)d_in[10];
    const float* b_G      = (const float*)d_in[11];
    const float* W_Oh     = (const float*)d_in[12];
    const float* b_Oh     = (const float*)d_in[13];
    const float* ffn_ln_h_g = (const float*)d_in[14];
    const float* ffn_ln_h_b = (const float*)d_in[15];
    const float* W_h1     = (const float*)d_in[16];
    const float* b_h1     = (const float*)d_in[17];
    const float* W_h2     = (const float*)d_in[18];
    const float* b_h2     = (const float*)d_in[19];
    const float* W_Oe     = (const float*)d_in[20];
    const float* b_Oe     = (const float*)d_in[21];
    const float* ffn_ln_e_g = (const float*)d_in[22];
    const float* ffn_ln_e_b = (const float*)d_in[23];
    const float* W_e1     = (const float*)d_in[24];
    const float* b_e1     = (const float*)d_in[25];
    const float* W_e2     = (const float*)d_in[26];
    const float* b_e2     = (const float*)d_in[27];

    float* out_h = (float*)d_out;
    float* out_e = out_h + H_OUT_ELEMS;

    float *p_hln, *p_qkv, *p_vatt, *p_h1, *p_h2, *p_act;
    cudaGetSymbolAddress((void**)&p_hln,  g_hln);
    cudaGetSymbolAddress((void**)&p_qkv,  g_qkv);
    cudaGetSymbolAddress((void**)&p_vatt, g_vatt);
    cudaGetSymbolAddress((void**)&p_h1,   g_h1);
    cudaGetSymbolAddress((void**)&p_h2,   g_h2);
    cudaGetSymbolAddress((void**)&p_act,  g_act);

    // h path pre-attention
    ln1024_kernel<<<BN, 256>>>(h, ln_h_g, ln_h_b, p_hln);
    gemm_tc_kernel<<<dim3(3*NDIM/128, BN/128), 256>>>(p_hln, W_QKV, b_QKV, nullptr, p_qkv,
                                                      BN, 3*NDIM, NDIM, 0);
    // e path: LN + E/G projections
    eg_kernel<<<(unsigned)(EROWS/64), 256>>>(e, ln_e_g, ln_e_b, W_E, b_E, W_G, b_G);
    // fused attention (tf32 mma)
    cudaFuncSetAttribute(av2_kernel, cudaFuncAttributeMaxDynamicSharedMemorySize,
                         AV2_SMEM * 4);
    av2_kernel<<<dim3(8, BHN), 256, AV2_SMEM * 4>>>(p_qkv);
    // h path post-attention
    gemm_tc_kernel<<<dim3(NDIM/128, BN/128), 256>>>(p_vatt, W_Oh, b_Oh, h, p_h1,
                                                    BN, NDIM, NDIM, 0);
    ln1024_kernel<<<BN, 256>>>(p_h1, ffn_ln_h_g, ffn_ln_h_b, p_h2);
    gemm_tc_kernel<<<dim3(FFN_H/128, BN/128), 256>>>(p_h2, W_h1, b_h1, nullptr, p_act,
                                                     BN, FFN_H, NDIM, 1);
    gemm_tc_kernel<<<dim3(NDIM/128, BN/128), 256>>>(p_act, W_h2, b_h2, p_h1, out_h,
                                                    BN, NDIM, FFN_H, 0);
    // fused e output path (persistent, weights staged once per (b,l))
    cudaFuncSetAttribute(eout_kernel, cudaFuncAttributeMaxDynamicSharedMemorySize,
                         EOUT_SMEM_FLOATS * 4);
    eout_kernel<<<BN, 256, EOUT_SMEM_FLOATS * 4>>>(
        e, W_Oe, b_Oe, ffn_ln_e_g, ffn_ln_e_b, W_e1, b_e1, W_e2, b_e2, out_e);
}